// round 13
// baseline (speedup 1.0000x reference)
#include <cuda_runtime.h>
#include <cuda_bf16.h>
#include <math.h>
#include <stdint.h>

#define SEQ      4096
#define HID      2048
#define NH       16
#define HD       128
#define HALF_WIN 256
#define NGLOB    16
#define SCALE    0.08838834764831845f   // 128^-0.5

// GEMM tiling (mma.sync path)
#define KCH        32
#define NKCHUNK    (HID / KCH)       // 64
#define STAGE_B    32768             // Ah 8K | Al 8K | Bh 8K | Bl 8K
#define NSTAGES    3
#define GEMM_SMEM  (NSTAGES * STAGE_B)   // 98304

// Attention smem: Qhi 32K | Qlo 32K | 2 KV stages (Khi|Klo|Vhi|Vlo = 64K each)
#define ATTN_SMEM  (65536 + 2 * 65536)   // 196608

// Single dynamic-smem declaration shared by all kernels in this TU.
extern __shared__ __align__(1024) char dyn_smem[];

// ---------------------------------------------------------------------------
// Scratch (device globals: allocation-free rule)
// ---------------------------------------------------------------------------
__device__ __nv_bfloat16 g_Xhi[SEQ * HID], g_Xlo[SEQ * HID];
__device__ __nv_bfloat16 g_Qhi[SEQ * HID], g_Qlo[SEQ * HID];
__device__ __nv_bfloat16 g_Khi[SEQ * HID], g_Klo[SEQ * HID];
__device__ __nv_bfloat16 g_Vhi[SEQ * HID], g_Vlo[SEQ * HID];
__device__ __nv_bfloat16 g_AOhi[SEQ * HID], g_AOlo[SEQ * HID];
__device__ __nv_bfloat16 g_Wqhi[HID * HID], g_Wqlo[HID * HID];
__device__ __nv_bfloat16 g_Wkhi[HID * HID], g_Wklo[HID * HID];
__device__ __nv_bfloat16 g_Wvhi[HID * HID], g_Wvlo[HID * HID];
__device__ __nv_bfloat16 g_Wohi[HID * HID], g_Wolo[HID * HID];

// ---------------------------------------------------------------------------
// Helpers (sm_80-compatible PTX only: cp.async, ldmatrix, mma.sync)
// ---------------------------------------------------------------------------
__device__ __forceinline__ uint32_t smem_u32(const void* p) {
    uint32_t a;
    asm("{ .reg .u64 t; cvta.to.shared.u64 t, %1; cvt.u32.u64 %0, t; }" : "=r"(a) : "l"(p));
    return a;
}

__device__ __forceinline__ void cp16(uint32_t dst, const void* src) {
    asm volatile("cp.async.cg.shared.global [%0], [%1], 16;" :: "r"(dst), "l"(src));
}
#define CP_COMMIT() asm volatile("cp.async.commit_group;" ::: "memory")
#define CP_WAIT1()  asm volatile("cp.async.wait_group 1;" ::: "memory")
#define CP_WAIT0()  asm volatile("cp.async.wait_group 0;" ::: "memory")

#define LDSM_X4(r0, r1, r2, r3, addr) \
    asm volatile("ldmatrix.sync.aligned.m8n8.x4.shared.b16 {%0,%1,%2,%3}, [%4];" \
                 : "=r"(r0), "=r"(r1), "=r"(r2), "=r"(r3) : "r"(addr))

#define LDSM_X4_T(r0, r1, r2, r3, addr) \
    asm volatile("ldmatrix.sync.aligned.m8n8.x4.trans.shared.b16 {%0,%1,%2,%3}, [%4];" \
                 : "=r"(r0), "=r"(r1), "=r"(r2), "=r"(r3) : "r"(addr))

#define MMA_BF16(d, a, b) \
    asm volatile("mma.sync.aligned.m16n8k16.row.col.f32.bf16.bf16.f32 " \
                 "{%0,%1,%2,%3}, {%4,%5,%6,%7}, {%8,%9}, {%0,%1,%2,%3};" \
                 : "+f"((d)[0]), "+f"((d)[1]), "+f"((d)[2]), "+f"((d)[3]) \
                 : "r"((a)[0]), "r"((a)[1]), "r"((a)[2]), "r"((a)[3]), \
                   "r"((b)[0]), "r"((b)[1]))

__device__ __forceinline__ uint32_t pack_bf2(__nv_bfloat16 a, __nv_bfloat16 b) {
    return (uint32_t)__bfloat16_as_ushort(a) | ((uint32_t)__bfloat16_as_ushort(b) << 16);
}
__device__ __forceinline__ uint32_t pack_hi(float x, float y) {
    return pack_bf2(__float2bfloat16_rn(x), __float2bfloat16_rn(y));
}
__device__ __forceinline__ uint32_t pack_lo(float x, float y) {
    __nv_bfloat16 hx = __float2bfloat16_rn(x), hy = __float2bfloat16_rn(y);
    return pack_bf2(__float2bfloat16_rn(x - __bfloat162float(hx)),
                    __float2bfloat16_rn(y - __bfloat162float(hy)));
}

// ---------------------------------------------------------------------------
// Merged hi/lo split: one launch covers X (2 y-slices) + 4 weight matrices.
// ---------------------------------------------------------------------------
__global__ __launch_bounds__(256) void split_all_kernel(
    const float* __restrict__ X,  __nv_bfloat16* __restrict__ xh,  __nv_bfloat16* __restrict__ xl,
    const float* __restrict__ W0, __nv_bfloat16* __restrict__ w0h, __nv_bfloat16* __restrict__ w0l,
    const float* __restrict__ W1, __nv_bfloat16* __restrict__ w1h, __nv_bfloat16* __restrict__ w1l,
    const float* __restrict__ W2, __nv_bfloat16* __restrict__ w2h, __nv_bfloat16* __restrict__ w2l,
    const float* __restrict__ W3, __nv_bfloat16* __restrict__ w3h, __nv_bfloat16* __restrict__ w3l)
{
    const int y = blockIdx.y;
    const float* src;
    __nv_bfloat16 *hi, *lo;
    size_t base = 0;
    switch (y) {
        case 0: src = X;  hi = xh;  lo = xl;  break;
        case 1: src = X;  hi = xh;  lo = xl;  base = (size_t)4096 * 1024; break;
        case 2: src = W0; hi = w0h; lo = w0l; break;
        case 3: src = W1; hi = w1h; lo = w1l; break;
        case 4: src = W2; hi = w2h; lo = w2l; break;
        default: src = W3; hi = w3h; lo = w3l; break;
    }
    size_t i = base + ((size_t)blockIdx.x * 256 + threadIdx.x) * 4;
    float4 x = *(const float4*)(src + i);
    float xs[4] = {x.x, x.y, x.z, x.w};
    __nv_bfloat16 h[4], l[4];
#pragma unroll
    for (int j = 0; j < 4; j++) {
        h[j] = __float2bfloat16_rn(xs[j]);
        l[j] = __float2bfloat16_rn(xs[j] - __bfloat162float(h[j]));
    }
    *(uint2*)(hi + i) = make_uint2(pack_bf2(h[0], h[1]), pack_bf2(h[2], h[3]));
    *(uint2*)(lo + i) = make_uint2(pack_bf2(l[0], l[1]), pack_bf2(l[2], l[3]));
}

// ---------------------------------------------------------------------------
// GEMM chunk loader
// ---------------------------------------------------------------------------
__device__ __forceinline__ void load_chunk(
    uint32_t sbase,
    const __nv_bfloat16* __restrict__ Ahi, const __nv_bfloat16* __restrict__ Alo,
    const __nv_bfloat16* __restrict__ Bhi, const __nv_bfloat16* __restrict__ Blo,
    int mtile, int ntile, int kc, int tid)
{
#pragma unroll
    for (int i = 0; i < 2; i++) {
        int unit = tid + i * 256;
        int r = unit >> 2, u = unit & 3;
        uint32_t dst = sbase + r * 64 + ((u ^ ((r >> 1) & 3)) << 4);
        size_t g = (size_t)(mtile * 128 + r) * HID + kc * KCH + u * 8;
        cp16(dst,        Ahi + g);
        cp16(dst + 8192, Alo + g);
    }
#pragma unroll
    for (int i = 0; i < 2; i++) {
        int unit = tid + i * 256;
        int r = unit >> 4, u = unit & 15;
        uint32_t dst = sbase + 16384 + r * 256 + ((u ^ (r & 7)) << 4);
        size_t g = (size_t)(kc * KCH + r) * HID + ntile * 128 + u * 8;
        cp16(dst,        Bhi + g);
        cp16(dst + 8192, Blo + g);
    }
}

// ---------------------------------------------------------------------------
// bf16 mma.sync GEMM body, 3-term hi/lo compensation.
// Reordered pipeline: wait(c) -> sync -> prefetch(c+2) -> compute(c).
// One barrier per chunk; cp.async overlaps the full compute.
// ---------------------------------------------------------------------------
template<bool SPLIT>
__device__ __forceinline__ void gemm_body(
    const __nv_bfloat16* __restrict__ Ahi, const __nv_bfloat16* __restrict__ Alo,
    const __nv_bfloat16* __restrict__ Bhi, const __nv_bfloat16* __restrict__ Blo,
    float* __restrict__ C,
    __nv_bfloat16* __restrict__ Ohi, __nv_bfloat16* __restrict__ Olo,
    int ntile, int mtile)
{
    const uint32_t sb = smem_u32(dyn_smem);
    const int tid  = threadIdx.x;
    const int lane = tid & 31;
    const int wid  = tid >> 5;
    const int wm = (wid & 1) * 64;
    const int wn = (wid >> 1) * 32;

    float acc[4][4][4];
#pragma unroll
    for (int a = 0; a < 4; a++)
#pragma unroll
        for (int b = 0; b < 4; b++)
#pragma unroll
            for (int c = 0; c < 4; c++) acc[a][b][c] = 0.0f;

    // prologue: chunks 0,1 (one commit group each)
#pragma unroll
    for (int s = 0; s < 2; s++) {
        load_chunk(sb + s * STAGE_B, Ahi, Alo, Bhi, Blo, mtile, ntile, s, tid);
        CP_COMMIT();
    }

    for (int c = 0; c < NKCHUNK; c++) {
        const int s = c % NSTAGES;
        const uint32_t sA  = sb + s * STAGE_B;
        const uint32_t sBh = sA + 16384;

        CP_WAIT1();            // chunk c resident
        __syncthreads();       // all warps done with chunk c-1; stage (c+2)%3 free

        const int cn = c + 2;
        if (cn < NKCHUNK)
            load_chunk(sb + (cn % NSTAGES) * STAGE_B, Ahi, Alo, Bhi, Blo,
                       mtile, ntile, cn, tid);
        CP_COMMIT();

#pragma unroll
        for (int ks = 0; ks < KCH; ks += 16) {
            uint32_t ah[4][4], bh[4][2], bl[4][2];

            const int brow = ks + (lane & 7) + ((lane >> 3) & 1) * 8;
            const int bnh  = (lane >> 4) * 8;
#pragma unroll
            for (int p = 0; p < 2; p++) {
                const int ncol = wn + p * 16 + bnh;
                uint32_t addr = sBh + brow * 256 + (((ncol >> 3) ^ (brow & 7)) << 4);
                uint32_t r0, r1, r2, r3;
                LDSM_X4_T(r0, r1, r2, r3, addr);
                bh[2 * p][0] = r0; bh[2 * p][1] = r1;
                bh[2 * p + 1][0] = r2; bh[2 * p + 1][1] = r3;
                LDSM_X4_T(r0, r1, r2, r3, addr + 8192);
                bl[2 * p][0] = r0; bl[2 * p][1] = r1;
                bl[2 * p + 1][0] = r2; bl[2 * p + 1][1] = r3;
            }

            const int au = (ks >> 3) + (lane >> 4);
#pragma unroll
            for (int mi = 0; mi < 4; mi++) {
                const int m = wm + mi * 16 + (lane & 15);
                uint32_t addr = sA + m * 64 + ((au ^ ((m >> 1) & 3)) << 4);
                LDSM_X4(ah[mi][0], ah[mi][1], ah[mi][2], ah[mi][3], addr);
            }
#pragma unroll
            for (int mi = 0; mi < 4; mi++)
#pragma unroll
                for (int ni = 0; ni < 4; ni++) {
                    MMA_BF16(acc[mi][ni], ah[mi], bh[ni]);
                    MMA_BF16(acc[mi][ni], ah[mi], bl[ni]);
                }
#pragma unroll
            for (int mi = 0; mi < 4; mi++) {
                const int m = wm + mi * 16 + (lane & 15);
                uint32_t addr = sA + 8192 + m * 64 + ((au ^ ((m >> 1) & 3)) << 4);
                LDSM_X4(ah[mi][0], ah[mi][1], ah[mi][2], ah[mi][3], addr);
            }
#pragma unroll
            for (int mi = 0; mi < 4; mi++)
#pragma unroll
                for (int ni = 0; ni < 4; ni++)
                    MMA_BF16(acc[mi][ni], ah[mi], bh[ni]);
        }
    }

    const size_t cbase = (size_t)(mtile * 128) * HID + ntile * 128;
#pragma unroll
    for (int mi = 0; mi < 4; mi++) {
#pragma unroll
        for (int ni = 0; ni < 4; ni++) {
            const int r0  = wm + mi * 16 + (lane >> 2);
            const int col = wn + ni * 8 + (lane & 3) * 2;
            const size_t i0 = cbase + (size_t)r0 * HID + col;
            const size_t i1 = i0 + 8 * HID;
            if (SPLIT) {
                *(uint32_t*)&Ohi[i0] = pack_hi(acc[mi][ni][0], acc[mi][ni][1]);
                *(uint32_t*)&Olo[i0] = pack_lo(acc[mi][ni][0], acc[mi][ni][1]);
                *(uint32_t*)&Ohi[i1] = pack_hi(acc[mi][ni][2], acc[mi][ni][3]);
                *(uint32_t*)&Olo[i1] = pack_lo(acc[mi][ni][2], acc[mi][ni][3]);
            } else {
                *(float2*)&C[i0] = make_float2(acc[mi][ni][0], acc[mi][ni][1]);
                *(float2*)&C[i1] = make_float2(acc[mi][ni][2], acc[mi][ni][3]);
            }
        }
    }
}

// QKV: one launch, grid (16, 32, 3); z selects weight + destination.
__global__ __launch_bounds__(256, 2) void qkv_gemm_kernel(
    const __nv_bfloat16* __restrict__ Ahi, const __nv_bfloat16* __restrict__ Alo,
    const __nv_bfloat16* __restrict__ W0h, const __nv_bfloat16* __restrict__ W0l,
    __nv_bfloat16* __restrict__ O0h, __nv_bfloat16* __restrict__ O0l,
    const __nv_bfloat16* __restrict__ W1h, const __nv_bfloat16* __restrict__ W1l,
    __nv_bfloat16* __restrict__ O1h, __nv_bfloat16* __restrict__ O1l,
    const __nv_bfloat16* __restrict__ W2h, const __nv_bfloat16* __restrict__ W2l,
    __nv_bfloat16* __restrict__ O2h, __nv_bfloat16* __restrict__ O2l)
{
    const __nv_bfloat16 *bh, *bl;
    __nv_bfloat16 *oh, *ol;
    if (blockIdx.z == 0)      { bh = W0h; bl = W0l; oh = O0h; ol = O0l; }
    else if (blockIdx.z == 1) { bh = W1h; bl = W1l; oh = O1h; ol = O1l; }
    else                      { bh = W2h; bl = W2l; oh = O2h; ol = O2l; }
    gemm_body<true>(Ahi, Alo, bh, bl, nullptr, oh, ol, blockIdx.x, blockIdx.y);
}

__global__ __launch_bounds__(256, 2) void out_gemm_kernel(
    const __nv_bfloat16* __restrict__ Ahi, const __nv_bfloat16* __restrict__ Alo,
    const __nv_bfloat16* __restrict__ Bhi, const __nv_bfloat16* __restrict__ Blo,
    float* __restrict__ C)
{
    gemm_body<false>(Ahi, Alo, Bhi, Blo, C, nullptr, nullptr, blockIdx.x, blockIdx.y);
}

// ---------------------------------------------------------------------------
// Flash attention, mma.sync bf16 with hi/lo compensation.
// Reordered loop: wait(curr) -> sync -> prefetch(next) -> compute(curr).
// ---------------------------------------------------------------------------
__device__ __forceinline__ void attn_load_kv(
    uint32_t kvb, int t, int tid, int h,
    const __nv_bfloat16* __restrict__ Khi, const __nv_bfloat16* __restrict__ Klo,
    const __nv_bfloat16* __restrict__ Vhi, const __nv_bfloat16* __restrict__ Vlo)
{
#pragma unroll
    for (int i = 0; i < 4; i++) {
        int u = tid + 256 * i;
        int r = u >> 4, c = u & 15;
        size_t g = (size_t)(t * 64 + r) * HID + h * HD + c * 8;
        uint32_t dst = kvb + r * 256 + ((c ^ (r & 7)) << 4);
        cp16(dst,         Khi + g);
        cp16(dst + 16384, Klo + g);
        cp16(dst + 32768, Vhi + g);
        cp16(dst + 49152, Vlo + g);
    }
}

__global__ __launch_bounds__(256, 1) void attn_mma_kernel(
    const __nv_bfloat16* __restrict__ Qhi, const __nv_bfloat16* __restrict__ Qlo,
    const __nv_bfloat16* __restrict__ Khi, const __nv_bfloat16* __restrict__ Klo,
    const __nv_bfloat16* __restrict__ Vhi, const __nv_bfloat16* __restrict__ Vlo,
    __nv_bfloat16* __restrict__ Ohi, __nv_bfloat16* __restrict__ Olo)
{
    const uint32_t sb = smem_u32(dyn_smem);
    const uint32_t SQ = sb;                     // Qhi 32K, Qlo at +32768
    const int tid = threadIdx.x, lane = tid & 31, wid = tid >> 5;
    const int wm = wid * 16;
    const int q0 = blockIdx.x * 128;
    const int h  = blockIdx.y;
    const int lr = lane & 15, lc = (lane >> 4) * 8;

    // Q tile load (hi+lo)
#pragma unroll
    for (int i = 0; i < 8; i++) {
        int u = tid + 256 * i;
        int r = u >> 4, c = u & 15;
        size_t g = (size_t)(q0 + r) * HID + h * HD + c * 8;
        uint32_t dst = SQ + r * 256 + ((c ^ (r & 7)) << 4);
        cp16(dst,         Qhi + g);
        cp16(dst + 32768, Qlo + g);
    }
    CP_COMMIT();

    int t_lo, t_hi;
    {
        int lo = q0 - (HALF_WIN - 1);
        t_lo = (lo < 64) ? 1 : (lo >> 6);
        t_hi = (q0 + 127 + HALF_WIN - 1) >> 6;
        if (t_hi > 63) t_hi = 63;
    }
    // block x==0: continue past band so warp 0 (global rows 0..15) sees all keys
    const int n_tiles = (q0 == 0) ? 64 : (t_hi - t_lo + 2);

    attn_load_kv(sb + 65536, 0, tid, h, Khi, Klo, Vhi, Vlo);
    CP_COMMIT();

    float m0 = -INFINITY, m1 = -INFINITY, l0 = 0.0f, l1 = 0.0f;
    float ov[16][4];
#pragma unroll
    for (int n = 0; n < 16; n++)
#pragma unroll
        for (int c = 0; c < 4; c++) ov[n][c] = 0.0f;

    const int r0g = q0 + wm + (lane >> 2);
    const int r1g = r0g + 8;

    for (int it = 0; it < n_tiles; it++) {
        const int s = it & 1;
        const uint32_t kvb = sb + 65536 + s * 65536;

        CP_WAIT0();            // current tile (and Q on it=0) resident
        __syncthreads();       // all warps done with previous tile; other stage free

        if (it + 1 < n_tiles) {
            attn_load_kv(sb + 65536 + (s ^ 1) * 65536, t_lo + it, tid, h,
                         Khi, Klo, Vhi, Vlo);
            CP_COMMIT();
        }

        const int t   = (it == 0) ? 0 : (t_lo + it - 1);
        const int kv0 = t << 6;
        const bool far = (q0 == 0) && (t > t_hi);

        if (!far || wid == 0) {
            // ---- S = Q K^T (3-term) ----
            float sv[8][4];
#pragma unroll
            for (int j = 0; j < 8; j++)
#pragma unroll
                for (int c = 0; c < 4; c++) sv[j][c] = 0.0f;

#pragma unroll
            for (int ks = 0; ks < 8; ks++) {
                uint32_t qh[4], ql[4];
                {
                    int r = wm + lr, d = 16 * ks + lc;
                    uint32_t a = SQ + r * 256 + (((d >> 3) ^ (r & 7)) << 4);
                    LDSM_X4(qh[0], qh[1], qh[2], qh[3], a);
                    LDSM_X4(ql[0], ql[1], ql[2], ql[3], a + 32768);
                }
#pragma unroll
                for (int j4 = 0; j4 < 4; j4++) {
                    uint32_t kh[4], kl[4];
                    int r = 16 * j4 + lr, d = 16 * ks + lc;
                    uint32_t a = kvb + r * 256 + (((d >> 3) ^ (r & 7)) << 4);
                    LDSM_X4(kh[0], kh[1], kh[2], kh[3], a);
                    LDSM_X4(kl[0], kl[1], kl[2], kl[3], a + 16384);
                    uint32_t b0[2] = {kh[0], kh[2]}, b1[2] = {kh[1], kh[3]};
                    uint32_t c0[2] = {kl[0], kl[2]}, c1[2] = {kl[1], kl[3]};
                    MMA_BF16(sv[2 * j4],     qh, b0);
                    MMA_BF16(sv[2 * j4],     qh, c0);
                    MMA_BF16(sv[2 * j4],     ql, b0);
                    MMA_BF16(sv[2 * j4 + 1], qh, b1);
                    MMA_BF16(sv[2 * j4 + 1], qh, c1);
                    MMA_BF16(sv[2 * j4 + 1], ql, b1);
                }
            }

            // ---- scale + mask ----
#pragma unroll
            for (int j = 0; j < 8; j++) {
                const int kc = kv0 + 8 * j + (lane & 3) * 2;
#pragma unroll
                for (int c = 0; c < 4; c++) {
                    const int qi = (c < 2) ? r0g : r1g;
                    const int kj = kc + (c & 1);
                    const int d  = qi - kj;
                    const bool ok = (d < HALF_WIN && d > -HALF_WIN) ||
                                    (qi < NGLOB) || (kj < NGLOB);
                    sv[j][c] = ok ? sv[j][c] * SCALE : -INFINITY;
                }
            }

            // ---- online softmax (2 rows per thread) ----
            float mx0 = -INFINITY, mx1 = -INFINITY;
#pragma unroll
            for (int j = 0; j < 8; j++) {
                mx0 = fmaxf(mx0, fmaxf(sv[j][0], sv[j][1]));
                mx1 = fmaxf(mx1, fmaxf(sv[j][2], sv[j][3]));
            }
            mx0 = fmaxf(mx0, __shfl_xor_sync(0xffffffffu, mx0, 1));
            mx0 = fmaxf(mx0, __shfl_xor_sync(0xffffffffu, mx0, 2));
            mx1 = fmaxf(mx1, __shfl_xor_sync(0xffffffffu, mx1, 1));
            mx1 = fmaxf(mx1, __shfl_xor_sync(0xffffffffu, mx1, 2));

            const float mn0 = fmaxf(m0, mx0), mn1 = fmaxf(m1, mx1);
            const float cr0 = __expf(m0 - mn0), cr1 = __expf(m1 - mn1);
            float s0 = 0.0f, s1 = 0.0f;
#pragma unroll
            for (int j = 0; j < 8; j++) {
                sv[j][0] = __expf(sv[j][0] - mn0);
                sv[j][1] = __expf(sv[j][1] - mn0);
                sv[j][2] = __expf(sv[j][2] - mn1);
                sv[j][3] = __expf(sv[j][3] - mn1);
                s0 += sv[j][0] + sv[j][1];
                s1 += sv[j][2] + sv[j][3];
            }
            s0 += __shfl_xor_sync(0xffffffffu, s0, 1);
            s0 += __shfl_xor_sync(0xffffffffu, s0, 2);
            s1 += __shfl_xor_sync(0xffffffffu, s1, 1);
            s1 += __shfl_xor_sync(0xffffffffu, s1, 2);
            l0 = l0 * cr0 + s0;  m0 = mn0;
            l1 = l1 * cr1 + s1;  m1 = mn1;
#pragma unroll
            for (int n = 0; n < 16; n++) {
                ov[n][0] *= cr0; ov[n][1] *= cr0;
                ov[n][2] *= cr1; ov[n][3] *= cr1;
            }

            // ---- P fragments (hi/lo) directly from S registers ----
            uint32_t phi[4][4], plo[4][4];
#pragma unroll
            for (int t2 = 0; t2 < 4; t2++) {
                phi[t2][0] = pack_hi(sv[2 * t2][0],     sv[2 * t2][1]);
                plo[t2][0] = pack_lo(sv[2 * t2][0],     sv[2 * t2][1]);
                phi[t2][1] = pack_hi(sv[2 * t2][2],     sv[2 * t2][3]);
                plo[t2][1] = pack_lo(sv[2 * t2][2],     sv[2 * t2][3]);
                phi[t2][2] = pack_hi(sv[2 * t2 + 1][0], sv[2 * t2 + 1][1]);
                plo[t2][2] = pack_lo(sv[2 * t2 + 1][0], sv[2 * t2 + 1][1]);
                phi[t2][3] = pack_hi(sv[2 * t2 + 1][2], sv[2 * t2 + 1][3]);
                plo[t2][3] = pack_lo(sv[2 * t2 + 1][2], sv[2 * t2 + 1][3]);
            }

            // ---- O += P V (3-term) ----
#pragma unroll
            for (int t2 = 0; t2 < 4; t2++) {
#pragma unroll
                for (int jj = 0; jj < 8; jj++) {
                    uint32_t vh[4], vl[4];
                    int r = 16 * t2 + lr, d = 16 * jj + lc;
                    uint32_t a = kvb + 32768 + r * 256 + (((d >> 3) ^ (r & 7)) << 4);
                    LDSM_X4_T(vh[0], vh[1], vh[2], vh[3], a);
                    LDSM_X4_T(vl[0], vl[1], vl[2], vl[3], a + 16384);
                    uint32_t b0[2] = {vh[0], vh[1]}, b1[2] = {vh[2], vh[3]};
                    uint32_t c0[2] = {vl[0], vl[1]}, c1[2] = {vl[2], vl[3]};
                    MMA_BF16(ov[2 * jj],     phi[t2], b0);
                    MMA_BF16(ov[2 * jj],     plo[t2], b0);
                    MMA_BF16(ov[2 * jj],     phi[t2], c0);
                    MMA_BF16(ov[2 * jj + 1], phi[t2], b1);
                    MMA_BF16(ov[2 * jj + 1], plo[t2], b1);
                    MMA_BF16(ov[2 * jj + 1], phi[t2], c1);
                }
            }
        }
    }

    // ---- epilogue: normalize and write hi/lo bf16 ----
    const float inv0 = 1.0f / l0, inv1 = 1.0f / l1;
    const size_t base0 = (size_t)r0g * HID + h * HD + (lane & 3) * 2;
    const size_t base1 = base0 + (size_t)8 * HID;
#pragma unroll
    for (int n = 0; n < 16; n++) {
        float x0 = ov[n][0] * inv0, x1 = ov[n][1] * inv0;
        float y0 = ov[n][2] * inv1, y1 = ov[n][3] * inv1;
        *(uint32_t*)&Ohi[base0 + 8 * n] = pack_hi(x0, x1);
        *(uint32_t*)&Olo[base0 + 8 * n] = pack_lo(x0, x1);
        *(uint32_t*)&Ohi[base1 + 8 * n] = pack_hi(y0, y1);
        *(uint32_t*)&Olo[base1 + 8 * n] = pack_lo(y0, y1);
    }
}

// ---------------------------------------------------------------------------

extern "C" void kernel_launch(void* const* d_in, const int* in_sizes, int n_in,
                              void* d_out, int out_size)
{
    const float* X  = (const float*)d_in[0];
    const float* Wq = (const float*)d_in[1];
    const float* Wk = (const float*)d_in[2];
    const float* Wv = (const float*)d_in[3];
    const float* Wo = (const float*)d_in[4];
    float* out = (float*)d_out;

    __nv_bfloat16 *xhi, *xlo, *qhi, *qlo, *khi, *klo, *vhi, *vlo, *aohi, *aolo;
    __nv_bfloat16 *wqh, *wql, *wkh, *wkl, *wvh, *wvl, *woh, *wol;
    cudaGetSymbolAddress((void**)&xhi,  g_Xhi);
    cudaGetSymbolAddress((void**)&xlo,  g_Xlo);
    cudaGetSymbolAddress((void**)&qhi,  g_Qhi);
    cudaGetSymbolAddress((void**)&qlo,  g_Qlo);
    cudaGetSymbolAddress((void**)&khi,  g_Khi);
    cudaGetSymbolAddress((void**)&klo,  g_Klo);
    cudaGetSymbolAddress((void**)&vhi,  g_Vhi);
    cudaGetSymbolAddress((void**)&vlo,  g_Vlo);
    cudaGetSymbolAddress((void**)&aohi, g_AOhi);
    cudaGetSymbolAddress((void**)&aolo, g_AOlo);
    cudaGetSymbolAddress((void**)&wqh,  g_Wqhi);
    cudaGetSymbolAddress((void**)&wql,  g_Wqlo);
    cudaGetSymbolAddress((void**)&wkh,  g_Wkhi);
    cudaGetSymbolAddress((void**)&wkl,  g_Wklo);
    cudaGetSymbolAddress((void**)&wvh,  g_Wvhi);
    cudaGetSymbolAddress((void**)&wvl,  g_Wvlo);
    cudaGetSymbolAddress((void**)&woh,  g_Wohi);
    cudaGetSymbolAddress((void**)&wol,  g_Wolo);

    cudaFuncSetAttribute(qkv_gemm_kernel,
                         cudaFuncAttributeMaxDynamicSharedMemorySize, GEMM_SMEM);
    cudaFuncSetAttribute(out_gemm_kernel,
                         cudaFuncAttributeMaxDynamicSharedMemorySize, GEMM_SMEM);
    cudaFuncSetAttribute(attn_mma_kernel,
                         cudaFuncAttributeMaxDynamicSharedMemorySize, ATTN_SMEM);

    split_all_kernel<<<dim3(4096, 6), 256>>>(
        X, xhi, xlo, Wq, wqh, wql, Wk, wkh, wkl, Wv, wvh, wvl, Wo, woh, wol);

    qkv_gemm_kernel<<<dim3(HID / 128, SEQ / 128, 3), 256, GEMM_SMEM>>>(
        xhi, xlo,
        wqh, wql, qhi, qlo,
        wkh, wkl, khi, klo,
        wvh, wvl, vhi, vlo);

    attn_mma_kernel<<<dim3(SEQ / 128, NH), 256, ATTN_SMEM>>>(
        qhi, qlo, khi, klo, vhi, vlo, aohi, aolo);

    out_gemm_kernel<<<dim3(HID / 128, SEQ / 128), 256, GEMM_SMEM>>>(
        aohi, aolo, woh, wol, out);
}

// round 15
// speedup vs baseline: 1.5259x; 1.5259x over previous
#include <cuda_runtime.h>
#include <cuda_bf16.h>
#include <math.h>
#include <stdint.h>

#define SEQ      4096
#define HID      2048
#define NH       16
#define HD       128
#define HALF_WIN 256
#define NGLOB    16
#define SCALE    0.08838834764831845f   // 128^-0.5

// GEMM tiling (mma.sync path)
#define KCH        32
#define NKCHUNK    (HID / KCH)       // 64
#define STAGE_B    32768             // Ah 8K | Al 8K | Bh 8K | Bl 8K
#define NSTAGES    3
#define GEMM_SMEM  (NSTAGES * STAGE_B)   // 98304

// Attention smem: Qhi 32K | Qlo 32K | 2 KV stages (Khi|Klo|Vhi|Vlo = 64K each)
#define ATTN_SMEM  (65536 + 2 * 65536)   // 196608

// Single dynamic-smem declaration shared by all kernels in this TU.
extern __shared__ __align__(1024) char dyn_smem[];

// ---------------------------------------------------------------------------
// Scratch (device globals: allocation-free rule)
// ---------------------------------------------------------------------------
__device__ __nv_bfloat16 g_Xhi[SEQ * HID], g_Xlo[SEQ * HID];
__device__ __nv_bfloat16 g_Qhi[SEQ * HID], g_Qlo[SEQ * HID];
__device__ __nv_bfloat16 g_Khi[SEQ * HID], g_Klo[SEQ * HID];
__device__ __nv_bfloat16 g_Vhi[SEQ * HID], g_Vlo[SEQ * HID];
__device__ __nv_bfloat16 g_AOhi[SEQ * HID], g_AOlo[SEQ * HID];
__device__ __nv_bfloat16 g_Wqhi[HID * HID], g_Wqlo[HID * HID];
__device__ __nv_bfloat16 g_Wkhi[HID * HID], g_Wklo[HID * HID];
__device__ __nv_bfloat16 g_Wvhi[HID * HID], g_Wvlo[HID * HID];
__device__ __nv_bfloat16 g_Wohi[HID * HID], g_Wolo[HID * HID];

// ---------------------------------------------------------------------------
// Helpers (sm_80-compatible PTX only: cp.async, ldmatrix, mma.sync)
// ---------------------------------------------------------------------------
__device__ __forceinline__ uint32_t smem_u32(const void* p) {
    uint32_t a;
    asm("{ .reg .u64 t; cvta.to.shared.u64 t, %1; cvt.u32.u64 %0, t; }" : "=r"(a) : "l"(p));
    return a;
}

__device__ __forceinline__ void cp16(uint32_t dst, const void* src) {
    asm volatile("cp.async.cg.shared.global [%0], [%1], 16;" :: "r"(dst), "l"(src));
}
#define CP_COMMIT() asm volatile("cp.async.commit_group;" ::: "memory")
#define CP_WAIT2()  asm volatile("cp.async.wait_group 2;" ::: "memory")
#define CP_WAIT1()  asm volatile("cp.async.wait_group 1;" ::: "memory")

#define LDSM_X4(r0, r1, r2, r3, addr) \
    asm volatile("ldmatrix.sync.aligned.m8n8.x4.shared.b16 {%0,%1,%2,%3}, [%4];" \
                 : "=r"(r0), "=r"(r1), "=r"(r2), "=r"(r3) : "r"(addr))

#define LDSM_X4_T(r0, r1, r2, r3, addr) \
    asm volatile("ldmatrix.sync.aligned.m8n8.x4.trans.shared.b16 {%0,%1,%2,%3}, [%4];" \
                 : "=r"(r0), "=r"(r1), "=r"(r2), "=r"(r3) : "r"(addr))

#define MMA_BF16(d, a, b) \
    asm volatile("mma.sync.aligned.m16n8k16.row.col.f32.bf16.bf16.f32 " \
                 "{%0,%1,%2,%3}, {%4,%5,%6,%7}, {%8,%9}, {%0,%1,%2,%3};" \
                 : "+f"((d)[0]), "+f"((d)[1]), "+f"((d)[2]), "+f"((d)[3]) \
                 : "r"((a)[0]), "r"((a)[1]), "r"((a)[2]), "r"((a)[3]), \
                   "r"((b)[0]), "r"((b)[1]))

__device__ __forceinline__ uint32_t pack_bf2(__nv_bfloat16 a, __nv_bfloat16 b) {
    return (uint32_t)__bfloat16_as_ushort(a) | ((uint32_t)__bfloat16_as_ushort(b) << 16);
}
__device__ __forceinline__ uint32_t pack_hi(float x, float y) {
    return pack_bf2(__float2bfloat16_rn(x), __float2bfloat16_rn(y));
}
__device__ __forceinline__ uint32_t pack_lo(float x, float y) {
    __nv_bfloat16 hx = __float2bfloat16_rn(x), hy = __float2bfloat16_rn(y);
    return pack_bf2(__float2bfloat16_rn(x - __bfloat162float(hx)),
                    __float2bfloat16_rn(y - __bfloat162float(hy)));
}

// ---------------------------------------------------------------------------
// Merged hi/lo split: one launch covers X (2 y-slices) + 4 weight matrices.
// ---------------------------------------------------------------------------
__global__ __launch_bounds__(256) void split_all_kernel(
    const float* __restrict__ X,  __nv_bfloat16* __restrict__ xh,  __nv_bfloat16* __restrict__ xl,
    const float* __restrict__ W0, __nv_bfloat16* __restrict__ w0h, __nv_bfloat16* __restrict__ w0l,
    const float* __restrict__ W1, __nv_bfloat16* __restrict__ w1h, __nv_bfloat16* __restrict__ w1l,
    const float* __restrict__ W2, __nv_bfloat16* __restrict__ w2h, __nv_bfloat16* __restrict__ w2l,
    const float* __restrict__ W3, __nv_bfloat16* __restrict__ w3h, __nv_bfloat16* __restrict__ w3l)
{
    const int y = blockIdx.y;
    const float* src;
    __nv_bfloat16 *hi, *lo;
    size_t base = 0;
    switch (y) {
        case 0: src = X;  hi = xh;  lo = xl;  break;
        case 1: src = X;  hi = xh;  lo = xl;  base = (size_t)4096 * 1024; break;
        case 2: src = W0; hi = w0h; lo = w0l; break;
        case 3: src = W1; hi = w1h; lo = w1l; break;
        case 4: src = W2; hi = w2h; lo = w2l; break;
        default: src = W3; hi = w3h; lo = w3l; break;
    }
    size_t i = base + ((size_t)blockIdx.x * 256 + threadIdx.x) * 4;
    float4 x = *(const float4*)(src + i);
    float xs[4] = {x.x, x.y, x.z, x.w};
    __nv_bfloat16 h[4], l[4];
#pragma unroll
    for (int j = 0; j < 4; j++) {
        h[j] = __float2bfloat16_rn(xs[j]);
        l[j] = __float2bfloat16_rn(xs[j] - __bfloat162float(h[j]));
    }
    *(uint2*)(hi + i) = make_uint2(pack_bf2(h[0], h[1]), pack_bf2(h[2], h[3]));
    *(uint2*)(lo + i) = make_uint2(pack_bf2(l[0], l[1]), pack_bf2(l[2], l[3]));
}

// ---------------------------------------------------------------------------
// GEMM chunk loader
// ---------------------------------------------------------------------------
__device__ __forceinline__ void load_chunk(
    uint32_t sbase,
    const __nv_bfloat16* __restrict__ Ahi, const __nv_bfloat16* __restrict__ Alo,
    const __nv_bfloat16* __restrict__ Bhi, const __nv_bfloat16* __restrict__ Blo,
    int mtile, int ntile, int kc, int tid)
{
#pragma unroll
    for (int i = 0; i < 2; i++) {
        int unit = tid + i * 256;
        int r = unit >> 2, u = unit & 3;
        uint32_t dst = sbase + r * 64 + ((u ^ ((r >> 1) & 3)) << 4);
        size_t g = (size_t)(mtile * 128 + r) * HID + kc * KCH + u * 8;
        cp16(dst,        Ahi + g);
        cp16(dst + 8192, Alo + g);
    }
#pragma unroll
    for (int i = 0; i < 2; i++) {
        int unit = tid + i * 256;
        int r = unit >> 4, u = unit & 15;
        uint32_t dst = sbase + 16384 + r * 256 + ((u ^ (r & 7)) << 4);
        size_t g = (size_t)(kc * KCH + r) * HID + ntile * 128 + u * 8;
        cp16(dst,        Bhi + g);
        cp16(dst + 8192, Blo + g);
    }
}

// ---------------------------------------------------------------------------
// bf16 mma.sync GEMM body, 3-term hi/lo compensation.
// R12 pipeline (measured best): wait2 -> sync -> compute -> sync -> load c+3.
// ---------------------------------------------------------------------------
template<bool SPLIT>
__device__ __forceinline__ void gemm_body(
    const __nv_bfloat16* __restrict__ Ahi, const __nv_bfloat16* __restrict__ Alo,
    const __nv_bfloat16* __restrict__ Bhi, const __nv_bfloat16* __restrict__ Blo,
    float* __restrict__ C,
    __nv_bfloat16* __restrict__ Ohi, __nv_bfloat16* __restrict__ Olo,
    int ntile, int mtile)
{
    const uint32_t sb = smem_u32(dyn_smem);
    const int tid  = threadIdx.x;
    const int lane = tid & 31;
    const int wid  = tid >> 5;
    const int wm = (wid & 1) * 64;
    const int wn = (wid >> 1) * 32;

    float acc[4][4][4];
#pragma unroll
    for (int a = 0; a < 4; a++)
#pragma unroll
        for (int b = 0; b < 4; b++)
#pragma unroll
            for (int c = 0; c < 4; c++) acc[a][b][c] = 0.0f;

#pragma unroll
    for (int s = 0; s < NSTAGES; s++) {
        load_chunk(sb + s * STAGE_B, Ahi, Alo, Bhi, Blo, mtile, ntile, s, tid);
        CP_COMMIT();
    }

    for (int c = 0; c < NKCHUNK; c++) {
        const int s = c % NSTAGES;
        const uint32_t sA  = sb + s * STAGE_B;
        const uint32_t sBh = sA + 16384;

        CP_WAIT2();
        __syncthreads();

#pragma unroll
        for (int ks = 0; ks < KCH; ks += 16) {
            uint32_t ah[4][4], bh[4][2], bl[4][2];

            const int brow = ks + (lane & 7) + ((lane >> 3) & 1) * 8;
            const int bnh  = (lane >> 4) * 8;
#pragma unroll
            for (int p = 0; p < 2; p++) {
                const int ncol = wn + p * 16 + bnh;
                uint32_t addr = sBh + brow * 256 + (((ncol >> 3) ^ (brow & 7)) << 4);
                uint32_t r0, r1, r2, r3;
                LDSM_X4_T(r0, r1, r2, r3, addr);
                bh[2 * p][0] = r0; bh[2 * p][1] = r1;
                bh[2 * p + 1][0] = r2; bh[2 * p + 1][1] = r3;
                LDSM_X4_T(r0, r1, r2, r3, addr + 8192);
                bl[2 * p][0] = r0; bl[2 * p][1] = r1;
                bl[2 * p + 1][0] = r2; bl[2 * p + 1][1] = r3;
            }

            const int au = (ks >> 3) + (lane >> 4);
#pragma unroll
            for (int mi = 0; mi < 4; mi++) {
                const int m = wm + mi * 16 + (lane & 15);
                uint32_t addr = sA + m * 64 + ((au ^ ((m >> 1) & 3)) << 4);
                LDSM_X4(ah[mi][0], ah[mi][1], ah[mi][2], ah[mi][3], addr);
            }
#pragma unroll
            for (int mi = 0; mi < 4; mi++)
#pragma unroll
                for (int ni = 0; ni < 4; ni++) {
                    MMA_BF16(acc[mi][ni], ah[mi], bh[ni]);
                    MMA_BF16(acc[mi][ni], ah[mi], bl[ni]);
                }
#pragma unroll
            for (int mi = 0; mi < 4; mi++) {
                const int m = wm + mi * 16 + (lane & 15);
                uint32_t addr = sA + 8192 + m * 64 + ((au ^ ((m >> 1) & 3)) << 4);
                LDSM_X4(ah[mi][0], ah[mi][1], ah[mi][2], ah[mi][3], addr);
            }
#pragma unroll
            for (int mi = 0; mi < 4; mi++)
#pragma unroll
                for (int ni = 0; ni < 4; ni++)
                    MMA_BF16(acc[mi][ni], ah[mi], bh[ni]);
        }

        __syncthreads();
        const int cn = c + NSTAGES;
        if (cn < NKCHUNK)
            load_chunk(sb + s * STAGE_B, Ahi, Alo, Bhi, Blo, mtile, ntile, cn, tid);
        CP_COMMIT();
    }

    const size_t cbase = (size_t)(mtile * 128) * HID + ntile * 128;
#pragma unroll
    for (int mi = 0; mi < 4; mi++) {
#pragma unroll
        for (int ni = 0; ni < 4; ni++) {
            const int r0  = wm + mi * 16 + (lane >> 2);
            const int col = wn + ni * 8 + (lane & 3) * 2;
            const size_t i0 = cbase + (size_t)r0 * HID + col;
            const size_t i1 = i0 + 8 * HID;
            if (SPLIT) {
                *(uint32_t*)&Ohi[i0] = pack_hi(acc[mi][ni][0], acc[mi][ni][1]);
                *(uint32_t*)&Olo[i0] = pack_lo(acc[mi][ni][0], acc[mi][ni][1]);
                *(uint32_t*)&Ohi[i1] = pack_hi(acc[mi][ni][2], acc[mi][ni][3]);
                *(uint32_t*)&Olo[i1] = pack_lo(acc[mi][ni][2], acc[mi][ni][3]);
            } else {
                *(float2*)&C[i0] = make_float2(acc[mi][ni][0], acc[mi][ni][1]);
                *(float2*)&C[i1] = make_float2(acc[mi][ni][2], acc[mi][ni][3]);
            }
        }
    }
}

// QKV: one launch, grid (16, 32, 3); z selects weight + destination.
__global__ __launch_bounds__(256, 2) void qkv_gemm_kernel(
    const __nv_bfloat16* __restrict__ Ahi, const __nv_bfloat16* __restrict__ Alo,
    const __nv_bfloat16* __restrict__ W0h, const __nv_bfloat16* __restrict__ W0l,
    __nv_bfloat16* __restrict__ O0h, __nv_bfloat16* __restrict__ O0l,
    const __nv_bfloat16* __restrict__ W1h, const __nv_bfloat16* __restrict__ W1l,
    __nv_bfloat16* __restrict__ O1h, __nv_bfloat16* __restrict__ O1l,
    const __nv_bfloat16* __restrict__ W2h, const __nv_bfloat16* __restrict__ W2l,
    __nv_bfloat16* __restrict__ O2h, __nv_bfloat16* __restrict__ O2l)
{
    const __nv_bfloat16 *bh, *bl;
    __nv_bfloat16 *oh, *ol;
    if (blockIdx.z == 0)      { bh = W0h; bl = W0l; oh = O0h; ol = O0l; }
    else if (blockIdx.z == 1) { bh = W1h; bl = W1l; oh = O1h; ol = O1l; }
    else                      { bh = W2h; bl = W2l; oh = O2h; ol = O2l; }
    gemm_body<true>(Ahi, Alo, bh, bl, nullptr, oh, ol, blockIdx.x, blockIdx.y);
}

__global__ __launch_bounds__(256, 2) void out_gemm_kernel(
    const __nv_bfloat16* __restrict__ Ahi, const __nv_bfloat16* __restrict__ Alo,
    const __nv_bfloat16* __restrict__ Bhi, const __nv_bfloat16* __restrict__ Blo,
    float* __restrict__ C)
{
    gemm_body<false>(Ahi, Alo, Bhi, Blo, C, nullptr, nullptr, blockIdx.x, blockIdx.y);
}

// ---------------------------------------------------------------------------
// Flash attention, mma.sync bf16 with hi/lo compensation.
// R12 loop structure; Q fragments hoisted to registers (loaded once).
// ---------------------------------------------------------------------------
__device__ __forceinline__ void attn_load_kv(
    uint32_t kvb, int t, int tid, int h,
    const __nv_bfloat16* __restrict__ Khi, const __nv_bfloat16* __restrict__ Klo,
    const __nv_bfloat16* __restrict__ Vhi, const __nv_bfloat16* __restrict__ Vlo)
{
#pragma unroll
    for (int i = 0; i < 4; i++) {
        int u = tid + 256 * i;
        int r = u >> 4, c = u & 15;
        size_t g = (size_t)(t * 64 + r) * HID + h * HD + c * 8;
        uint32_t dst = kvb + r * 256 + ((c ^ (r & 7)) << 4);
        cp16(dst,         Khi + g);
        cp16(dst + 16384, Klo + g);
        cp16(dst + 32768, Vhi + g);
        cp16(dst + 49152, Vlo + g);
    }
}

__global__ __launch_bounds__(256, 1) void attn_mma_kernel(
    const __nv_bfloat16* __restrict__ Qhi, const __nv_bfloat16* __restrict__ Qlo,
    const __nv_bfloat16* __restrict__ Khi, const __nv_bfloat16* __restrict__ Klo,
    const __nv_bfloat16* __restrict__ Vhi, const __nv_bfloat16* __restrict__ Vlo,
    __nv_bfloat16* __restrict__ Ohi, __nv_bfloat16* __restrict__ Olo)
{
    const uint32_t sb = smem_u32(dyn_smem);
    const uint32_t SQ = sb;                     // Qhi 32K, Qlo at +32768
    const int tid = threadIdx.x, lane = tid & 31, wid = tid >> 5;
    const int wm = wid * 16;
    const int q0 = blockIdx.x * 128;
    const int h  = blockIdx.y;
    const int lr = lane & 15, lc = (lane >> 4) * 8;

    // Q tile load (hi+lo)
#pragma unroll
    for (int i = 0; i < 8; i++) {
        int u = tid + 256 * i;
        int r = u >> 4, c = u & 15;
        size_t g = (size_t)(q0 + r) * HID + h * HD + c * 8;
        uint32_t dst = SQ + r * 256 + ((c ^ (r & 7)) << 4);
        cp16(dst,         Qhi + g);
        cp16(dst + 32768, Qlo + g);
    }
    CP_COMMIT();

    int t_lo, t_hi;
    {
        int lo = q0 - (HALF_WIN - 1);
        t_lo = (lo < 64) ? 1 : (lo >> 6);
        t_hi = (q0 + 127 + HALF_WIN - 1) >> 6;
        if (t_hi > 63) t_hi = 63;
    }
    // block x==0: continue past band so warp 0 (global rows 0..15) sees all keys
    const int n_tiles = (q0 == 0) ? 64 : (t_hi - t_lo + 2);

    attn_load_kv(sb + 65536, 0, tid, h, Khi, Klo, Vhi, Vlo);
    CP_COMMIT();

    float m0 = -INFINITY, m1 = -INFINITY, l0 = 0.0f, l1 = 0.0f;
    float ov[16][4];
#pragma unroll
    for (int n = 0; n < 16; n++)
#pragma unroll
        for (int c = 0; c < 4; c++) ov[n][c] = 0.0f;

    uint32_t qfh[8][4], qfl[8][4];   // hoisted Q fragments (filled at it==0)

    const int r0g = q0 + wm + (lane >> 2);
    const int r1g = r0g + 8;

    for (int it = 0; it < n_tiles; it++) {
        const int s = it & 1;
        const uint32_t kvb = sb + 65536 + s * 65536;

        __syncthreads();               // prev compute done before stage reuse
        if (it + 1 < n_tiles)
            attn_load_kv(sb + 65536 + (s ^ 1) * 65536, t_lo + it, tid, h,
                         Khi, Klo, Vhi, Vlo);
        CP_COMMIT();
        CP_WAIT1();
        __syncthreads();               // current tile (and Q) visible

        if (it == 0) {
            // one-time Q fragment load into registers
#pragma unroll
            for (int ks = 0; ks < 8; ks++) {
                int r = wm + lr, d = 16 * ks + lc;
                uint32_t a = SQ + r * 256 + (((d >> 3) ^ (r & 7)) << 4);
                LDSM_X4(qfh[ks][0], qfh[ks][1], qfh[ks][2], qfh[ks][3], a);
                LDSM_X4(qfl[ks][0], qfl[ks][1], qfl[ks][2], qfl[ks][3], a + 32768);
            }
        }

        const int t   = (it == 0) ? 0 : (t_lo + it - 1);
        const int kv0 = t << 6;
        const bool far = (q0 == 0) && (t > t_hi);

        if (!far || wid == 0) {
            // ---- S = Q K^T (3-term) ----
            float sv[8][4];
#pragma unroll
            for (int j = 0; j < 8; j++)
#pragma unroll
                for (int c = 0; c < 4; c++) sv[j][c] = 0.0f;

#pragma unroll
            for (int ks = 0; ks < 8; ks++) {
#pragma unroll
                for (int j4 = 0; j4 < 4; j4++) {
                    uint32_t kh[4], kl[4];
                    int r = 16 * j4 + lr, d = 16 * ks + lc;
                    uint32_t a = kvb + r * 256 + (((d >> 3) ^ (r & 7)) << 4);
                    LDSM_X4(kh[0], kh[1], kh[2], kh[3], a);
                    LDSM_X4(kl[0], kl[1], kl[2], kl[3], a + 16384);
                    uint32_t b0[2] = {kh[0], kh[2]}, b1[2] = {kh[1], kh[3]};
                    uint32_t c0[2] = {kl[0], kl[2]}, c1[2] = {kl[1], kl[3]};
                    MMA_BF16(sv[2 * j4],     qfh[ks], b0);
                    MMA_BF16(sv[2 * j4],     qfh[ks], c0);
                    MMA_BF16(sv[2 * j4],     qfl[ks], b0);
                    MMA_BF16(sv[2 * j4 + 1], qfh[ks], b1);
                    MMA_BF16(sv[2 * j4 + 1], qfh[ks], c1);
                    MMA_BF16(sv[2 * j4 + 1], qfl[ks], b1);
                }
            }

            // ---- scale + mask ----
#pragma unroll
            for (int j = 0; j < 8; j++) {
                const int kc = kv0 + 8 * j + (lane & 3) * 2;
#pragma unroll
                for (int c = 0; c < 4; c++) {
                    const int qi = (c < 2) ? r0g : r1g;
                    const int kj = kc + (c & 1);
                    const int d  = qi - kj;
                    const bool ok = (d < HALF_WIN && d > -HALF_WIN) ||
                                    (qi < NGLOB) || (kj < NGLOB);
                    sv[j][c] = ok ? sv[j][c] * SCALE : -INFINITY;
                }
            }

            // ---- online softmax (2 rows per thread) ----
            float mx0 = -INFINITY, mx1 = -INFINITY;
#pragma unroll
            for (int j = 0; j < 8; j++) {
                mx0 = fmaxf(mx0, fmaxf(sv[j][0], sv[j][1]));
                mx1 = fmaxf(mx1, fmaxf(sv[j][2], sv[j][3]));
            }
            mx0 = fmaxf(mx0, __shfl_xor_sync(0xffffffffu, mx0, 1));
            mx0 = fmaxf(mx0, __shfl_xor_sync(0xffffffffu, mx0, 2));
            mx1 = fmaxf(mx1, __shfl_xor_sync(0xffffffffu, mx1, 1));
            mx1 = fmaxf(mx1, __shfl_xor_sync(0xffffffffu, mx1, 2));

            const float mn0 = fmaxf(m0, mx0), mn1 = fmaxf(m1, mx1);
            const float cr0 = __expf(m0 - mn0), cr1 = __expf(m1 - mn1);
            float s0 = 0.0f, s1 = 0.0f;
#pragma unroll
            for (int j = 0; j < 8; j++) {
                sv[j][0] = __expf(sv[j][0] - mn0);
                sv[j][1] = __expf(sv[j][1] - mn0);
                sv[j][2] = __expf(sv[j][2] - mn1);
                sv[j][3] = __expf(sv[j][3] - mn1);
                s0 += sv[j][0] + sv[j][1];
                s1 += sv[j][2] + sv[j][3];
            }
            s0 += __shfl_xor_sync(0xffffffffu, s0, 1);
            s0 += __shfl_xor_sync(0xffffffffu, s0, 2);
            s1 += __shfl_xor_sync(0xffffffffu, s1, 1);
            s1 += __shfl_xor_sync(0xffffffffu, s1, 2);
            l0 = l0 * cr0 + s0;  m0 = mn0;
            l1 = l1 * cr1 + s1;  m1 = mn1;
#pragma unroll
            for (int n = 0; n < 16; n++) {
                ov[n][0] *= cr0; ov[n][1] *= cr0;
                ov[n][2] *= cr1; ov[n][3] *= cr1;
            }

            // ---- P fragments (hi/lo) directly from S registers ----
            uint32_t phi[4][4], plo[4][4];
#pragma unroll
            for (int t2 = 0; t2 < 4; t2++) {
                phi[t2][0] = pack_hi(sv[2 * t2][0],     sv[2 * t2][1]);
                plo[t2][0] = pack_lo(sv[2 * t2][0],     sv[2 * t2][1]);
                phi[t2][1] = pack_hi(sv[2 * t2][2],     sv[2 * t2][3]);
                plo[t2][1] = pack_lo(sv[2 * t2][2],     sv[2 * t2][3]);
                phi[t2][2] = pack_hi(sv[2 * t2 + 1][0], sv[2 * t2 + 1][1]);
                plo[t2][2] = pack_lo(sv[2 * t2 + 1][0], sv[2 * t2 + 1][1]);
                phi[t2][3] = pack_hi(sv[2 * t2 + 1][2], sv[2 * t2 + 1][3]);
                plo[t2][3] = pack_lo(sv[2 * t2 + 1][2], sv[2 * t2 + 1][3]);
            }

            // ---- O += P V (3-term) ----
#pragma unroll
            for (int t2 = 0; t2 < 4; t2++) {
#pragma unroll
                for (int jj = 0; jj < 8; jj++) {
                    uint32_t vh[4], vl[4];
                    int r = 16 * t2 + lr, d = 16 * jj + lc;
                    uint32_t a = kvb + 32768 + r * 256 + (((d >> 3) ^ (r & 7)) << 4);
                    LDSM_X4_T(vh[0], vh[1], vh[2], vh[3], a);
                    LDSM_X4_T(vl[0], vl[1], vl[2], vl[3], a + 16384);
                    uint32_t b0[2] = {vh[0], vh[1]}, b1[2] = {vh[2], vh[3]};
                    uint32_t c0[2] = {vl[0], vl[1]}, c1[2] = {vl[2], vl[3]};
                    MMA_BF16(ov[2 * jj],     phi[t2], b0);
                    MMA_BF16(ov[2 * jj],     plo[t2], b0);
                    MMA_BF16(ov[2 * jj],     phi[t2], c0);
                    MMA_BF16(ov[2 * jj + 1], phi[t2], b1);
                    MMA_BF16(ov[2 * jj + 1], plo[t2], b1);
                    MMA_BF16(ov[2 * jj + 1], phi[t2], c1);
                }
            }
        }
    }

    // ---- epilogue: normalize and write hi/lo bf16 ----
    const float inv0 = 1.0f / l0, inv1 = 1.0f / l1;
    const size_t base0 = (size_t)r0g * HID + h * HD + (lane & 3) * 2;
    const size_t base1 = base0 + (size_t)8 * HID;
#pragma unroll
    for (int n = 0; n < 16; n++) {
        float x0 = ov[n][0] * inv0, x1 = ov[n][1] * inv0;
        float y0 = ov[n][2] * inv1, y1 = ov[n][3] * inv1;
        *(uint32_t*)&Ohi[base0 + 8 * n] = pack_hi(x0, x1);
        *(uint32_t*)&Olo[base0 + 8 * n] = pack_lo(x0, x1);
        *(uint32_t*)&Ohi[base1 + 8 * n] = pack_hi(y0, y1);
        *(uint32_t*)&Olo[base1 + 8 * n] = pack_lo(y0, y1);
    }
}

// ---------------------------------------------------------------------------

extern "C" void kernel_launch(void* const* d_in, const int* in_sizes, int n_in,
                              void* d_out, int out_size)
{
    const float* X  = (const float*)d_in[0];
    const float* Wq = (const float*)d_in[1];
    const float* Wk = (const float*)d_in[2];
    const float* Wv = (const float*)d_in[3];
    const float* Wo = (const float*)d_in[4];
    float* out = (float*)d_out;

    __nv_bfloat16 *xhi, *xlo, *qhi, *qlo, *khi, *klo, *vhi, *vlo, *aohi, *aolo;
    __nv_bfloat16 *wqh, *wql, *wkh, *wkl, *wvh, *wvl, *woh, *wol;
    cudaGetSymbolAddress((void**)&xhi,  g_Xhi);
    cudaGetSymbolAddress((void**)&xlo,  g_Xlo);
    cudaGetSymbolAddress((void**)&qhi,  g_Qhi);
    cudaGetSymbolAddress((void**)&qlo,  g_Qlo);
    cudaGetSymbolAddress((void**)&khi,  g_Khi);
    cudaGetSymbolAddress((void**)&klo,  g_Klo);
    cudaGetSymbolAddress((void**)&vhi,  g_Vhi);
    cudaGetSymbolAddress((void**)&vlo,  g_Vlo);
    cudaGetSymbolAddress((void**)&aohi, g_AOhi);
    cudaGetSymbolAddress((void**)&aolo, g_AOlo);
    cudaGetSymbolAddress((void**)&wqh,  g_Wqhi);
    cudaGetSymbolAddress((void**)&wql,  g_Wqlo);
    cudaGetSymbolAddress((void**)&wkh,  g_Wkhi);
    cudaGetSymbolAddress((void**)&wkl,  g_Wklo);
    cudaGetSymbolAddress((void**)&wvh,  g_Wvhi);
    cudaGetSymbolAddress((void**)&wvl,  g_Wvlo);
    cudaGetSymbolAddress((void**)&woh,  g_Wohi);
    cudaGetSymbolAddress((void**)&wol,  g_Wolo);

    cudaFuncSetAttribute(qkv_gemm_kernel,
                         cudaFuncAttributeMaxDynamicSharedMemorySize, GEMM_SMEM);
    cudaFuncSetAttribute(out_gemm_kernel,
                         cudaFuncAttributeMaxDynamicSharedMemorySize, GEMM_SMEM);
    cudaFuncSetAttribute(attn_mma_kernel,
                         cudaFuncAttributeMaxDynamicSharedMemorySize, ATTN_SMEM);

    split_all_kernel<<<dim3(4096, 6), 256>>>(
        X, xhi, xlo, Wq, wqh, wql, Wk, wkh, wkl, Wv, wvh, wvl, Wo, woh, wol);

    qkv_gemm_kernel<<<dim3(HID / 128, SEQ / 128, 3), 256, GEMM_SMEM>>>(
        xhi, xlo,
        wqh, wql, qhi, qlo,
        wkh, wkl, khi, klo,
        wvh, wvl, vhi, vlo);

    attn_mma_kernel<<<dim3(SEQ / 128, NH), 256, ATTN_SMEM>>>(
        qhi, qlo, khi, klo, vhi, vlo, aohi, aolo);

    out_gemm_kernel<<<dim3(HID / 128, SEQ / 128), 256, GEMM_SMEM>>>(
        aohi, aolo, woh, wol, out);
}

// round 16
// speedup vs baseline: 1.6191x; 1.0611x over previous
#include <cuda_runtime.h>
#include <cuda_bf16.h>
#include <math.h>
#include <stdint.h>

#define SEQ      4096
#define HID      2048
#define NH       16
#define HD       128
#define HALF_WIN 256
#define NGLOB    16
#define SCALE    0.08838834764831845f   // 128^-0.5

// GEMM tiling (mma.sync path)
#define KCH        32
#define NKCHUNK    (HID / KCH)       // 64
#define STAGE_B    32768             // Ah 8K | Al 8K | Bh 8K | Bl 8K
#define NSTAGES    3
#define GEMM_SMEM  (NSTAGES * STAGE_B)   // 98304

// Attention smem: Qhi 32K | Qlo 32K | 2 KV stages (64K each) | Qg 8K
#define ATTN_SMEM  (65536 + 2 * 65536 + 8192)   // 204800

// Single dynamic-smem declaration shared by all kernels in this TU.
extern __shared__ __align__(1024) char dyn_smem[];

// ---------------------------------------------------------------------------
// Scratch (device globals: allocation-free rule)
// ---------------------------------------------------------------------------
__device__ __nv_bfloat16 g_Xhi[SEQ * HID], g_Xlo[SEQ * HID];
__device__ __nv_bfloat16 g_Qhi[SEQ * HID], g_Qlo[SEQ * HID];
__device__ __nv_bfloat16 g_Khi[SEQ * HID], g_Klo[SEQ * HID];
__device__ __nv_bfloat16 g_Vhi[SEQ * HID], g_Vlo[SEQ * HID];
__device__ __nv_bfloat16 g_AOhi[SEQ * HID], g_AOlo[SEQ * HID];
__device__ __nv_bfloat16 g_Wqhi[HID * HID], g_Wqlo[HID * HID];
__device__ __nv_bfloat16 g_Wkhi[HID * HID], g_Wklo[HID * HID];
__device__ __nv_bfloat16 g_Wvhi[HID * HID], g_Wvlo[HID * HID];
__device__ __nv_bfloat16 g_Wohi[HID * HID], g_Wolo[HID * HID];

// Global-row partials: [head][xblock(32)][warp(8)] x [16 rows][128 dims]
__device__ float g_partO[NH * 32 * 8 * 16 * HD];
__device__ float g_partML[NH * 32 * 8 * 16 * 2];

// ---------------------------------------------------------------------------
// Helpers (sm_80-compatible PTX only: cp.async, ldmatrix, mma.sync)
// ---------------------------------------------------------------------------
__device__ __forceinline__ uint32_t smem_u32(const void* p) {
    uint32_t a;
    asm("{ .reg .u64 t; cvta.to.shared.u64 t, %1; cvt.u32.u64 %0, t; }" : "=r"(a) : "l"(p));
    return a;
}

__device__ __forceinline__ void cp16(uint32_t dst, const void* src) {
    asm volatile("cp.async.cg.shared.global [%0], [%1], 16;" :: "r"(dst), "l"(src));
}
#define CP_COMMIT() asm volatile("cp.async.commit_group;" ::: "memory")
#define CP_WAIT2()  asm volatile("cp.async.wait_group 2;" ::: "memory")
#define CP_WAIT1()  asm volatile("cp.async.wait_group 1;" ::: "memory")

#define LDSM_X4(r0, r1, r2, r3, addr) \
    asm volatile("ldmatrix.sync.aligned.m8n8.x4.shared.b16 {%0,%1,%2,%3}, [%4];" \
                 : "=r"(r0), "=r"(r1), "=r"(r2), "=r"(r3) : "r"(addr))

#define LDSM_X4_T(r0, r1, r2, r3, addr) \
    asm volatile("ldmatrix.sync.aligned.m8n8.x4.trans.shared.b16 {%0,%1,%2,%3}, [%4];" \
                 : "=r"(r0), "=r"(r1), "=r"(r2), "=r"(r3) : "r"(addr))

#define MMA_BF16(d, a, b) \
    asm volatile("mma.sync.aligned.m16n8k16.row.col.f32.bf16.bf16.f32 " \
                 "{%0,%1,%2,%3}, {%4,%5,%6,%7}, {%8,%9}, {%0,%1,%2,%3};" \
                 : "+f"((d)[0]), "+f"((d)[1]), "+f"((d)[2]), "+f"((d)[3]) \
                 : "r"((a)[0]), "r"((a)[1]), "r"((a)[2]), "r"((a)[3]), \
                   "r"((b)[0]), "r"((b)[1]))

__device__ __forceinline__ uint32_t pack_bf2(__nv_bfloat16 a, __nv_bfloat16 b) {
    return (uint32_t)__bfloat16_as_ushort(a) | ((uint32_t)__bfloat16_as_ushort(b) << 16);
}
__device__ __forceinline__ uint32_t pack_hi(float x, float y) {
    return pack_bf2(__float2bfloat16_rn(x), __float2bfloat16_rn(y));
}
__device__ __forceinline__ uint32_t pack_lo(float x, float y) {
    __nv_bfloat16 hx = __float2bfloat16_rn(x), hy = __float2bfloat16_rn(y);
    return pack_bf2(__float2bfloat16_rn(x - __bfloat162float(hx)),
                    __float2bfloat16_rn(y - __bfloat162float(hy)));
}

// ---------------------------------------------------------------------------
// Merged hi/lo split: one launch covers X (2 y-slices) + 4 weight matrices.
// ---------------------------------------------------------------------------
__global__ __launch_bounds__(256) void split_all_kernel(
    const float* __restrict__ X,  __nv_bfloat16* __restrict__ xh,  __nv_bfloat16* __restrict__ xl,
    const float* __restrict__ W0, __nv_bfloat16* __restrict__ w0h, __nv_bfloat16* __restrict__ w0l,
    const float* __restrict__ W1, __nv_bfloat16* __restrict__ w1h, __nv_bfloat16* __restrict__ w1l,
    const float* __restrict__ W2, __nv_bfloat16* __restrict__ w2h, __nv_bfloat16* __restrict__ w2l,
    const float* __restrict__ W3, __nv_bfloat16* __restrict__ w3h, __nv_bfloat16* __restrict__ w3l)
{
    const int y = blockIdx.y;
    const float* src;
    __nv_bfloat16 *hi, *lo;
    size_t base = 0;
    switch (y) {
        case 0: src = X;  hi = xh;  lo = xl;  break;
        case 1: src = X;  hi = xh;  lo = xl;  base = (size_t)4096 * 1024; break;
        case 2: src = W0; hi = w0h; lo = w0l; break;
        case 3: src = W1; hi = w1h; lo = w1l; break;
        case 4: src = W2; hi = w2h; lo = w2l; break;
        default: src = W3; hi = w3h; lo = w3l; break;
    }
    size_t i = base + ((size_t)blockIdx.x * 256 + threadIdx.x) * 4;
    float4 x = *(const float4*)(src + i);
    float xs[4] = {x.x, x.y, x.z, x.w};
    __nv_bfloat16 h[4], l[4];
#pragma unroll
    for (int j = 0; j < 4; j++) {
        h[j] = __float2bfloat16_rn(xs[j]);
        l[j] = __float2bfloat16_rn(xs[j] - __bfloat162float(h[j]));
    }
    *(uint2*)(hi + i) = make_uint2(pack_bf2(h[0], h[1]), pack_bf2(h[2], h[3]));
    *(uint2*)(lo + i) = make_uint2(pack_bf2(l[0], l[1]), pack_bf2(l[2], l[3]));
}

// ---------------------------------------------------------------------------
// GEMM chunk loader
// ---------------------------------------------------------------------------
__device__ __forceinline__ void load_chunk(
    uint32_t sbase,
    const __nv_bfloat16* __restrict__ Ahi, const __nv_bfloat16* __restrict__ Alo,
    const __nv_bfloat16* __restrict__ Bhi, const __nv_bfloat16* __restrict__ Blo,
    int mtile, int ntile, int kc, int tid)
{
#pragma unroll
    for (int i = 0; i < 2; i++) {
        int unit = tid + i * 256;
        int r = unit >> 2, u = unit & 3;
        uint32_t dst = sbase + r * 64 + ((u ^ ((r >> 1) & 3)) << 4);
        size_t g = (size_t)(mtile * 128 + r) * HID + kc * KCH + u * 8;
        cp16(dst,        Ahi + g);
        cp16(dst + 8192, Alo + g);
    }
#pragma unroll
    for (int i = 0; i < 2; i++) {
        int unit = tid + i * 256;
        int r = unit >> 4, u = unit & 15;
        uint32_t dst = sbase + 16384 + r * 256 + ((u ^ (r & 7)) << 4);
        size_t g = (size_t)(kc * KCH + r) * HID + ntile * 128 + u * 8;
        cp16(dst,        Bhi + g);
        cp16(dst + 8192, Blo + g);
    }
}

// ---------------------------------------------------------------------------
// bf16 mma.sync GEMM body, 3-term hi/lo compensation.
// R12 pipeline (measured best): wait2 -> sync -> compute -> sync -> load c+3.
// ---------------------------------------------------------------------------
template<bool SPLIT>
__device__ __forceinline__ void gemm_body(
    const __nv_bfloat16* __restrict__ Ahi, const __nv_bfloat16* __restrict__ Alo,
    const __nv_bfloat16* __restrict__ Bhi, const __nv_bfloat16* __restrict__ Blo,
    float* __restrict__ C,
    __nv_bfloat16* __restrict__ Ohi, __nv_bfloat16* __restrict__ Olo,
    int ntile, int mtile)
{
    const uint32_t sb = smem_u32(dyn_smem);
    const int tid  = threadIdx.x;
    const int lane = tid & 31;
    const int wid  = tid >> 5;
    const int wm = (wid & 1) * 64;
    const int wn = (wid >> 1) * 32;

    float acc[4][4][4];
#pragma unroll
    for (int a = 0; a < 4; a++)
#pragma unroll
        for (int b = 0; b < 4; b++)
#pragma unroll
            for (int c = 0; c < 4; c++) acc[a][b][c] = 0.0f;

#pragma unroll
    for (int s = 0; s < NSTAGES; s++) {
        load_chunk(sb + s * STAGE_B, Ahi, Alo, Bhi, Blo, mtile, ntile, s, tid);
        CP_COMMIT();
    }

    for (int c = 0; c < NKCHUNK; c++) {
        const int s = c % NSTAGES;
        const uint32_t sA  = sb + s * STAGE_B;
        const uint32_t sBh = sA + 16384;

        CP_WAIT2();
        __syncthreads();

#pragma unroll
        for (int ks = 0; ks < KCH; ks += 16) {
            uint32_t ah[4][4], bh[4][2], bl[4][2];

            const int brow = ks + (lane & 7) + ((lane >> 3) & 1) * 8;
            const int bnh  = (lane >> 4) * 8;
#pragma unroll
            for (int p = 0; p < 2; p++) {
                const int ncol = wn + p * 16 + bnh;
                uint32_t addr = sBh + brow * 256 + (((ncol >> 3) ^ (brow & 7)) << 4);
                uint32_t r0, r1, r2, r3;
                LDSM_X4_T(r0, r1, r2, r3, addr);
                bh[2 * p][0] = r0; bh[2 * p][1] = r1;
                bh[2 * p + 1][0] = r2; bh[2 * p + 1][1] = r3;
                LDSM_X4_T(r0, r1, r2, r3, addr + 8192);
                bl[2 * p][0] = r0; bl[2 * p][1] = r1;
                bl[2 * p + 1][0] = r2; bl[2 * p + 1][1] = r3;
            }

            const int au = (ks >> 3) + (lane >> 4);
#pragma unroll
            for (int mi = 0; mi < 4; mi++) {
                const int m = wm + mi * 16 + (lane & 15);
                uint32_t addr = sA + m * 64 + ((au ^ ((m >> 1) & 3)) << 4);
                LDSM_X4(ah[mi][0], ah[mi][1], ah[mi][2], ah[mi][3], addr);
            }
#pragma unroll
            for (int mi = 0; mi < 4; mi++)
#pragma unroll
                for (int ni = 0; ni < 4; ni++) {
                    MMA_BF16(acc[mi][ni], ah[mi], bh[ni]);
                    MMA_BF16(acc[mi][ni], ah[mi], bl[ni]);
                }
#pragma unroll
            for (int mi = 0; mi < 4; mi++) {
                const int m = wm + mi * 16 + (lane & 15);
                uint32_t addr = sA + 8192 + m * 64 + ((au ^ ((m >> 1) & 3)) << 4);
                LDSM_X4(ah[mi][0], ah[mi][1], ah[mi][2], ah[mi][3], addr);
            }
#pragma unroll
            for (int mi = 0; mi < 4; mi++)
#pragma unroll
                for (int ni = 0; ni < 4; ni++)
                    MMA_BF16(acc[mi][ni], ah[mi], bh[ni]);
        }

        __syncthreads();
        const int cn = c + NSTAGES;
        if (cn < NKCHUNK)
            load_chunk(sb + s * STAGE_B, Ahi, Alo, Bhi, Blo, mtile, ntile, cn, tid);
        CP_COMMIT();
    }

    const size_t cbase = (size_t)(mtile * 128) * HID + ntile * 128;
#pragma unroll
    for (int mi = 0; mi < 4; mi++) {
#pragma unroll
        for (int ni = 0; ni < 4; ni++) {
            const int r0  = wm + mi * 16 + (lane >> 2);
            const int col = wn + ni * 8 + (lane & 3) * 2;
            const size_t i0 = cbase + (size_t)r0 * HID + col;
            const size_t i1 = i0 + 8 * HID;
            if (SPLIT) {
                *(uint32_t*)&Ohi[i0] = pack_hi(acc[mi][ni][0], acc[mi][ni][1]);
                *(uint32_t*)&Olo[i0] = pack_lo(acc[mi][ni][0], acc[mi][ni][1]);
                *(uint32_t*)&Ohi[i1] = pack_hi(acc[mi][ni][2], acc[mi][ni][3]);
                *(uint32_t*)&Olo[i1] = pack_lo(acc[mi][ni][2], acc[mi][ni][3]);
            } else {
                *(float2*)&C[i0] = make_float2(acc[mi][ni][0], acc[mi][ni][1]);
                *(float2*)&C[i1] = make_float2(acc[mi][ni][2], acc[mi][ni][3]);
            }
        }
    }
}

// QKV: one launch, grid (16, 32, 3); z selects weight + destination.
__global__ __launch_bounds__(256, 2) void qkv_gemm_kernel(
    const __nv_bfloat16* __restrict__ Ahi, const __nv_bfloat16* __restrict__ Alo,
    const __nv_bfloat16* __restrict__ W0h, const __nv_bfloat16* __restrict__ W0l,
    __nv_bfloat16* __restrict__ O0h, __nv_bfloat16* __restrict__ O0l,
    const __nv_bfloat16* __restrict__ W1h, const __nv_bfloat16* __restrict__ W1l,
    __nv_bfloat16* __restrict__ O1h, __nv_bfloat16* __restrict__ O1l,
    const __nv_bfloat16* __restrict__ W2h, const __nv_bfloat16* __restrict__ W2l,
    __nv_bfloat16* __restrict__ O2h, __nv_bfloat16* __restrict__ O2l)
{
    const __nv_bfloat16 *bh, *bl;
    __nv_bfloat16 *oh, *ol;
    if (blockIdx.z == 0)      { bh = W0h; bl = W0l; oh = O0h; ol = O0l; }
    else if (blockIdx.z == 1) { bh = W1h; bl = W1l; oh = O1h; ol = O1l; }
    else                      { bh = W2h; bl = W2l; oh = O2h; ol = O2l; }
    gemm_body<true>(Ahi, Alo, bh, bl, nullptr, oh, ol, blockIdx.x, blockIdx.y);
}

__global__ __launch_bounds__(256, 2) void out_gemm_kernel(
    const __nv_bfloat16* __restrict__ Ahi, const __nv_bfloat16* __restrict__ Alo,
    const __nv_bfloat16* __restrict__ Bhi, const __nv_bfloat16* __restrict__ Blo,
    float* __restrict__ C)
{
    gemm_body<false>(Ahi, Alo, Bhi, Blo, C, nullptr, nullptr, blockIdx.x, blockIdx.y);
}

// ---------------------------------------------------------------------------
// Flash attention, mma.sync bf16 with hi/lo compensation (R12 structure).
// Global rows (0..15) handled via per-block partials over self key-tiles:
// block x owns keys [128x, 128x+128); warp w takes 16-key slice; partial
// (m, l, O) stored to scratch; reduce kernel merges. No straggler block.
// ---------------------------------------------------------------------------
__device__ __forceinline__ void attn_load_kv(
    uint32_t kvb, int t, int tid, int h,
    const __nv_bfloat16* __restrict__ Khi, const __nv_bfloat16* __restrict__ Klo,
    const __nv_bfloat16* __restrict__ Vhi, const __nv_bfloat16* __restrict__ Vlo)
{
#pragma unroll
    for (int i = 0; i < 4; i++) {
        int u = tid + 256 * i;
        int r = u >> 4, c = u & 15;
        size_t g = (size_t)(t * 64 + r) * HID + h * HD + c * 8;
        uint32_t dst = kvb + r * 256 + ((c ^ (r & 7)) << 4);
        cp16(dst,         Khi + g);
        cp16(dst + 16384, Klo + g);
        cp16(dst + 32768, Vhi + g);
        cp16(dst + 49152, Vlo + g);
    }
}

__global__ __launch_bounds__(256, 1) void attn_mma_kernel(
    const __nv_bfloat16* __restrict__ Qhi, const __nv_bfloat16* __restrict__ Qlo,
    const __nv_bfloat16* __restrict__ Khi, const __nv_bfloat16* __restrict__ Klo,
    const __nv_bfloat16* __restrict__ Vhi, const __nv_bfloat16* __restrict__ Vlo,
    __nv_bfloat16* __restrict__ Ohi, __nv_bfloat16* __restrict__ Olo)
{
    const uint32_t sb  = smem_u32(dyn_smem);
    const uint32_t SQ  = sb;                     // Qhi 32K, Qlo at +32768
    const uint32_t SQG = sb + 196608;            // global-row Q: hi 4K, lo 4K
    const int tid = threadIdx.x, lane = tid & 31, wid = tid >> 5;
    const int wm = wid * 16;
    const int q0 = blockIdx.x * 128;
    const int h  = blockIdx.y;
    const int lr = lane & 15, lc = (lane >> 4) * 8;

    // Q tile load (hi+lo) + global-row Q (rows 0..15)
#pragma unroll
    for (int i = 0; i < 8; i++) {
        int u = tid + 256 * i;
        int r = u >> 4, c = u & 15;
        size_t g = (size_t)(q0 + r) * HID + h * HD + c * 8;
        uint32_t dst = SQ + r * 256 + ((c ^ (r & 7)) << 4);
        cp16(dst,         Qhi + g);
        cp16(dst + 32768, Qlo + g);
    }
    {
        int r = tid >> 4, c = tid & 15;   // rows 0..15
        size_t g = (size_t)r * HID + h * HD + c * 8;
        uint32_t dst = SQG + r * 256 + ((c ^ (r & 7)) << 4);
        cp16(dst,        Qhi + g);
        cp16(dst + 4096, Qlo + g);
    }
    CP_COMMIT();

    int t_lo, t_hi;
    {
        int lo = q0 - (HALF_WIN - 1);
        t_lo = (lo < 64) ? 1 : (lo >> 6);
        t_hi = (q0 + 127 + HALF_WIN - 1) >> 6;
        if (t_hi > 63) t_hi = 63;
    }
    const int n_tiles = t_hi - t_lo + 2;   // tile(0)=0 (global keys), then band

    attn_load_kv(sb + 65536, 0, tid, h, Khi, Klo, Vhi, Vlo);
    CP_COMMIT();

    float m0 = -INFINITY, m1 = -INFINITY, l0 = 0.0f, l1 = 0.0f;
    float ov[16][4];
#pragma unroll
    for (int n = 0; n < 16; n++)
#pragma unroll
        for (int c = 0; c < 4; c++) ov[n][c] = 0.0f;

    const int r0g = q0 + wm + (lane >> 2);
    const int r1g = r0g + 8;
    const int t_self = 2 * blockIdx.x + (wid >> 2);   // this warp's global key tile
    const int troff  = (wid & 3) * 16;                // 16-key slice within tile

    for (int it = 0; it < n_tiles; it++) {
        const int s = it & 1;
        const uint32_t kvb = sb + 65536 + s * 65536;

        __syncthreads();               // prev compute done before stage reuse
        if (it + 1 < n_tiles)
            attn_load_kv(sb + 65536 + (s ^ 1) * 65536, t_lo + it, tid, h,
                         Khi, Klo, Vhi, Vlo);
        CP_COMMIT();
        CP_WAIT1();
        __syncthreads();               // current tile (and Q) visible

        const int t   = (it == 0) ? 0 : (t_lo + it - 1);
        const int kv0 = t << 6;

        // ---- S = Q K^T (3-term) ----
        float sv[8][4];
#pragma unroll
        for (int j = 0; j < 8; j++)
#pragma unroll
            for (int c = 0; c < 4; c++) sv[j][c] = 0.0f;

#pragma unroll
        for (int ks = 0; ks < 8; ks++) {
            uint32_t qh[4], ql[4];
            {
                int r = wm + lr, d = 16 * ks + lc;
                uint32_t a = SQ + r * 256 + (((d >> 3) ^ (r & 7)) << 4);
                LDSM_X4(qh[0], qh[1], qh[2], qh[3], a);
                LDSM_X4(ql[0], ql[1], ql[2], ql[3], a + 32768);
            }
#pragma unroll
            for (int j4 = 0; j4 < 4; j4++) {
                uint32_t kh[4], kl[4];
                int r = 16 * j4 + lr, d = 16 * ks + lc;
                uint32_t a = kvb + r * 256 + (((d >> 3) ^ (r & 7)) << 4);
                LDSM_X4(kh[0], kh[1], kh[2], kh[3], a);
                LDSM_X4(kl[0], kl[1], kl[2], kl[3], a + 16384);
                uint32_t b0[2] = {kh[0], kh[2]}, b1[2] = {kh[1], kh[3]};
                uint32_t c0[2] = {kl[0], kl[2]}, c1[2] = {kl[1], kl[3]};
                MMA_BF16(sv[2 * j4],     qh, b0);
                MMA_BF16(sv[2 * j4],     qh, c0);
                MMA_BF16(sv[2 * j4],     ql, b0);
                MMA_BF16(sv[2 * j4 + 1], qh, b1);
                MMA_BF16(sv[2 * j4 + 1], qh, c1);
                MMA_BF16(sv[2 * j4 + 1], ql, b1);
            }
        }

        // ---- scale + mask ----
#pragma unroll
        for (int j = 0; j < 8; j++) {
            const int kc = kv0 + 8 * j + (lane & 3) * 2;
#pragma unroll
            for (int c = 0; c < 4; c++) {
                const int qi = (c < 2) ? r0g : r1g;
                const int kj = kc + (c & 1);
                const int d  = qi - kj;
                const bool ok = (d < HALF_WIN && d > -HALF_WIN) ||
                                (qi < NGLOB) || (kj < NGLOB);
                sv[j][c] = ok ? sv[j][c] * SCALE : -INFINITY;
            }
        }

        // ---- online softmax (2 rows per thread) ----
        float mx0 = -INFINITY, mx1 = -INFINITY;
#pragma unroll
        for (int j = 0; j < 8; j++) {
            mx0 = fmaxf(mx0, fmaxf(sv[j][0], sv[j][1]));
            mx1 = fmaxf(mx1, fmaxf(sv[j][2], sv[j][3]));
        }
        mx0 = fmaxf(mx0, __shfl_xor_sync(0xffffffffu, mx0, 1));
        mx0 = fmaxf(mx0, __shfl_xor_sync(0xffffffffu, mx0, 2));
        mx1 = fmaxf(mx1, __shfl_xor_sync(0xffffffffu, mx1, 1));
        mx1 = fmaxf(mx1, __shfl_xor_sync(0xffffffffu, mx1, 2));

        const float mn0 = fmaxf(m0, mx0), mn1 = fmaxf(m1, mx1);
        const float cr0 = __expf(m0 - mn0), cr1 = __expf(m1 - mn1);
        float s0 = 0.0f, s1 = 0.0f;
#pragma unroll
        for (int j = 0; j < 8; j++) {
            sv[j][0] = __expf(sv[j][0] - mn0);
            sv[j][1] = __expf(sv[j][1] - mn0);
            sv[j][2] = __expf(sv[j][2] - mn1);
            sv[j][3] = __expf(sv[j][3] - mn1);
            s0 += sv[j][0] + sv[j][1];
            s1 += sv[j][2] + sv[j][3];
        }
        s0 += __shfl_xor_sync(0xffffffffu, s0, 1);
        s0 += __shfl_xor_sync(0xffffffffu, s0, 2);
        s1 += __shfl_xor_sync(0xffffffffu, s1, 1);
        s1 += __shfl_xor_sync(0xffffffffu, s1, 2);
        l0 = l0 * cr0 + s0;  m0 = mn0;
        l1 = l1 * cr1 + s1;  m1 = mn1;
#pragma unroll
        for (int n = 0; n < 16; n++) {
            ov[n][0] *= cr0; ov[n][1] *= cr0;
            ov[n][2] *= cr1; ov[n][3] *= cr1;
        }

        // ---- P fragments (hi/lo) directly from S registers ----
        uint32_t phi[4][4], plo[4][4];
#pragma unroll
        for (int t2 = 0; t2 < 4; t2++) {
            phi[t2][0] = pack_hi(sv[2 * t2][0],     sv[2 * t2][1]);
            plo[t2][0] = pack_lo(sv[2 * t2][0],     sv[2 * t2][1]);
            phi[t2][1] = pack_hi(sv[2 * t2][2],     sv[2 * t2][3]);
            plo[t2][1] = pack_lo(sv[2 * t2][2],     sv[2 * t2][3]);
            phi[t2][2] = pack_hi(sv[2 * t2 + 1][0], sv[2 * t2 + 1][1]);
            plo[t2][2] = pack_lo(sv[2 * t2 + 1][0], sv[2 * t2 + 1][1]);
            phi[t2][3] = pack_hi(sv[2 * t2 + 1][2], sv[2 * t2 + 1][3]);
            plo[t2][3] = pack_lo(sv[2 * t2 + 1][2], sv[2 * t2 + 1][3]);
        }

        // ---- O += P V (3-term) ----
#pragma unroll
        for (int t2 = 0; t2 < 4; t2++) {
#pragma unroll
            for (int jj = 0; jj < 8; jj++) {
                uint32_t vh[4], vl[4];
                int r = 16 * t2 + lr, d = 16 * jj + lc;
                uint32_t a = kvb + 32768 + r * 256 + (((d >> 3) ^ (r & 7)) << 4);
                LDSM_X4_T(vh[0], vh[1], vh[2], vh[3], a);
                LDSM_X4_T(vl[0], vl[1], vl[2], vl[3], a + 16384);
                uint32_t b0[2] = {vh[0], vh[1]}, b1[2] = {vh[2], vh[3]};
                uint32_t c0[2] = {vl[0], vl[1]}, c1[2] = {vl[2], vl[3]};
                MMA_BF16(ov[2 * jj],     phi[t2], b0);
                MMA_BF16(ov[2 * jj],     plo[t2], b0);
                MMA_BF16(ov[2 * jj],     phi[t2], c0);
                MMA_BF16(ov[2 * jj + 1], phi[t2], b1);
                MMA_BF16(ov[2 * jj + 1], plo[t2], b1);
                MMA_BF16(ov[2 * jj + 1], phi[t2], c1);
            }
        }

        // ---- global-row partial over this warp's 16-key slice ----
        if (t == t_self) {
            float sg[2][4];
#pragma unroll
            for (int j = 0; j < 2; j++)
#pragma unroll
                for (int c = 0; c < 4; c++) sg[j][c] = 0.0f;

#pragma unroll
            for (int ks = 0; ks < 8; ks++) {
                uint32_t qgh[4], qgl[4], kh[4], kl[4];
                int d = 16 * ks + lc;
                uint32_t qa = SQG + lr * 256 + (((d >> 3) ^ (lr & 7)) << 4);
                LDSM_X4(qgh[0], qgh[1], qgh[2], qgh[3], qa);
                LDSM_X4(qgl[0], qgl[1], qgl[2], qgl[3], qa + 4096);
                int r = troff + lr;
                uint32_t ka = kvb + r * 256 + (((d >> 3) ^ (r & 7)) << 4);
                LDSM_X4(kh[0], kh[1], kh[2], kh[3], ka);
                LDSM_X4(kl[0], kl[1], kl[2], kl[3], ka + 16384);
                uint32_t b0[2] = {kh[0], kh[2]}, b1[2] = {kh[1], kh[3]};
                uint32_t c0[2] = {kl[0], kl[2]}, c1[2] = {kl[1], kl[3]};
                MMA_BF16(sg[0], qgh, b0);
                MMA_BF16(sg[0], qgh, c0);
                MMA_BF16(sg[0], qgl, b0);
                MMA_BF16(sg[1], qgh, b1);
                MMA_BF16(sg[1], qgh, c1);
                MMA_BF16(sg[1], qgl, b1);
            }
#pragma unroll
            for (int j = 0; j < 2; j++)
#pragma unroll
                for (int c = 0; c < 4; c++) sg[j][c] *= SCALE;

            // local softmax over 16 keys (no mask: global rows see all keys)
            float mg0 = fmaxf(fmaxf(sg[0][0], sg[0][1]), fmaxf(sg[1][0], sg[1][1]));
            float mg1 = fmaxf(fmaxf(sg[0][2], sg[0][3]), fmaxf(sg[1][2], sg[1][3]));
            mg0 = fmaxf(mg0, __shfl_xor_sync(0xffffffffu, mg0, 1));
            mg0 = fmaxf(mg0, __shfl_xor_sync(0xffffffffu, mg0, 2));
            mg1 = fmaxf(mg1, __shfl_xor_sync(0xffffffffu, mg1, 1));
            mg1 = fmaxf(mg1, __shfl_xor_sync(0xffffffffu, mg1, 2));
            float lg0 = 0.0f, lg1 = 0.0f;
#pragma unroll
            for (int j = 0; j < 2; j++) {
                sg[j][0] = __expf(sg[j][0] - mg0);
                sg[j][1] = __expf(sg[j][1] - mg0);
                sg[j][2] = __expf(sg[j][2] - mg1);
                sg[j][3] = __expf(sg[j][3] - mg1);
                lg0 += sg[j][0] + sg[j][1];
                lg1 += sg[j][2] + sg[j][3];
            }
            lg0 += __shfl_xor_sync(0xffffffffu, lg0, 1);
            lg0 += __shfl_xor_sync(0xffffffffu, lg0, 2);
            lg1 += __shfl_xor_sync(0xffffffffu, lg1, 1);
            lg1 += __shfl_xor_sync(0xffffffffu, lg1, 2);

            uint32_t pgh[4], pgl[4];
            pgh[0] = pack_hi(sg[0][0], sg[0][1]); pgl[0] = pack_lo(sg[0][0], sg[0][1]);
            pgh[1] = pack_hi(sg[0][2], sg[0][3]); pgl[1] = pack_lo(sg[0][2], sg[0][3]);
            pgh[2] = pack_hi(sg[1][0], sg[1][1]); pgl[2] = pack_lo(sg[1][0], sg[1][1]);
            pgh[3] = pack_hi(sg[1][2], sg[1][3]); pgl[3] = pack_lo(sg[1][2], sg[1][3]);

            float og[16][4];
#pragma unroll
            for (int n = 0; n < 16; n++)
#pragma unroll
                for (int c = 0; c < 4; c++) og[n][c] = 0.0f;

#pragma unroll
            for (int nf = 0; nf < 8; nf++) {
                uint32_t vh[4], vl[4];
                int r = troff + lr, d = 16 * nf + lc;
                uint32_t a = kvb + 32768 + r * 256 + (((d >> 3) ^ (r & 7)) << 4);
                LDSM_X4_T(vh[0], vh[1], vh[2], vh[3], a);
                LDSM_X4_T(vl[0], vl[1], vl[2], vl[3], a + 16384);
                uint32_t b0[2] = {vh[0], vh[1]}, b1[2] = {vh[2], vh[3]};
                uint32_t c0[2] = {vl[0], vl[1]}, c1[2] = {vl[2], vl[3]};
                MMA_BF16(og[2 * nf],     pgh, b0);
                MMA_BF16(og[2 * nf],     pgl, b0);
                MMA_BF16(og[2 * nf],     pgh, c0);
                MMA_BF16(og[2 * nf + 1], pgh, b1);
                MMA_BF16(og[2 * nf + 1], pgl, b1);
                MMA_BF16(og[2 * nf + 1], pgh, c1);
            }

            // store partial (unnormalized) + (m,l)
            const int r0l = lane >> 2, c0l = (lane & 3) * 2;
            float* PB = g_partO +
                (size_t)(((h * 32 + blockIdx.x) * 8) + wid) * (16 * HD);
#pragma unroll
            for (int n = 0; n < 16; n++) {
                *(float2*)&PB[r0l * HD + n * 8 + c0l] =
                    make_float2(og[n][0], og[n][1]);
                *(float2*)&PB[(r0l + 8) * HD + n * 8 + c0l] =
                    make_float2(og[n][2], og[n][3]);
            }
            if ((lane & 3) == 0) {
                float* MB = g_partML +
                    (size_t)((((h * 32 + blockIdx.x) * 8) + wid) * 16) * 2;
                MB[r0l * 2]           = mg0;
                MB[r0l * 2 + 1]       = lg0;
                MB[(r0l + 8) * 2]     = mg1;
                MB[(r0l + 8) * 2 + 1] = lg1;
            }
        }
    }

    // ---- epilogue: normalize and write hi/lo bf16 ----
    // block 0 / warp 0 covers global rows 0..15 -> written by reduce kernel
    if (!(q0 == 0 && wid == 0)) {
        const float inv0 = 1.0f / l0, inv1 = 1.0f / l1;
        const size_t base0 = (size_t)r0g * HID + h * HD + (lane & 3) * 2;
        const size_t base1 = base0 + (size_t)8 * HID;
#pragma unroll
        for (int n = 0; n < 16; n++) {
            float x0 = ov[n][0] * inv0, x1 = ov[n][1] * inv0;
            float y0 = ov[n][2] * inv1, y1 = ov[n][3] * inv1;
            *(uint32_t*)&Ohi[base0 + 8 * n] = pack_hi(x0, x1);
            *(uint32_t*)&Olo[base0 + 8 * n] = pack_lo(x0, x1);
            *(uint32_t*)&Ohi[base1 + 8 * n] = pack_hi(y0, y1);
            *(uint32_t*)&Olo[base1 + 8 * n] = pack_lo(y0, y1);
        }
    }
}

// ---------------------------------------------------------------------------
// Merge 256 global-row partials per head; write rows 0..15 of AO.
// grid (NH, 16 rows), 128 threads (dims).
// ---------------------------------------------------------------------------
__global__ __launch_bounds__(128) void reduce_global_kernel(
    __nv_bfloat16* __restrict__ Ohi, __nv_bfloat16* __restrict__ Olo)
{
    __shared__ float sm[256], sl[256], swe[256];
    const int h = blockIdx.x, r = blockIdx.y, tid = threadIdx.x;

    for (int p = tid; p < 256; p += 128) {
        const float* MB = g_partML + ((size_t)(h * 256 + p) * 16 + r) * 2;
        sm[p] = MB[0];
        sl[p] = MB[1];
    }
    __syncthreads();

    float M = -INFINITY;
#pragma unroll 8
    for (int p = 0; p < 256; p++) M = fmaxf(M, sm[p]);
    for (int p = tid; p < 256; p += 128) swe[p] = __expf(sm[p] - M);
    __syncthreads();

    float L = 0.0f;
#pragma unroll 8
    for (int p = 0; p < 256; p++) L += swe[p] * sl[p];

    float s = 0.0f;
#pragma unroll 4
    for (int p = 0; p < 256; p++)
        s += swe[p] * g_partO[((size_t)(h * 256 + p) * 16 + r) * HD + tid];

    const float o = s / L;
    const size_t idx = (size_t)r * HID + h * HD + tid;
    __nv_bfloat16 hi = __float2bfloat16_rn(o);
    Ohi[idx] = hi;
    Olo[idx] = __float2bfloat16_rn(o - __bfloat162float(hi));
}

// ---------------------------------------------------------------------------

extern "C" void kernel_launch(void* const* d_in, const int* in_sizes, int n_in,
                              void* d_out, int out_size)
{
    const float* X  = (const float*)d_in[0];
    const float* Wq = (const float*)d_in[1];
    const float* Wk = (const float*)d_in[2];
    const float* Wv = (const float*)d_in[3];
    const float* Wo = (const float*)d_in[4];
    float* out = (float*)d_out;

    __nv_bfloat16 *xhi, *xlo, *qhi, *qlo, *khi, *klo, *vhi, *vlo, *aohi, *aolo;
    __nv_bfloat16 *wqh, *wql, *wkh, *wkl, *wvh, *wvl, *woh, *wol;
    cudaGetSymbolAddress((void**)&xhi,  g_Xhi);
    cudaGetSymbolAddress((void**)&xlo,  g_Xlo);
    cudaGetSymbolAddress((void**)&qhi,  g_Qhi);
    cudaGetSymbolAddress((void**)&qlo,  g_Qlo);
    cudaGetSymbolAddress((void**)&khi,  g_Khi);
    cudaGetSymbolAddress((void**)&klo,  g_Klo);
    cudaGetSymbolAddress((void**)&vhi,  g_Vhi);
    cudaGetSymbolAddress((void**)&vlo,  g_Vlo);
    cudaGetSymbolAddress((void**)&aohi, g_AOhi);
    cudaGetSymbolAddress((void**)&aolo, g_AOlo);
    cudaGetSymbolAddress((void**)&wqh,  g_Wqhi);
    cudaGetSymbolAddress((void**)&wql,  g_Wqlo);
    cudaGetSymbolAddress((void**)&wkh,  g_Wkhi);
    cudaGetSymbolAddress((void**)&wkl,  g_Wklo);
    cudaGetSymbolAddress((void**)&wvh,  g_Wvhi);
    cudaGetSymbolAddress((void**)&wvl,  g_Wvlo);
    cudaGetSymbolAddress((void**)&woh,  g_Wohi);
    cudaGetSymbolAddress((void**)&wol,  g_Wolo);

    cudaFuncSetAttribute(qkv_gemm_kernel,
                         cudaFuncAttributeMaxDynamicSharedMemorySize, GEMM_SMEM);
    cudaFuncSetAttribute(out_gemm_kernel,
                         cudaFuncAttributeMaxDynamicSharedMemorySize, GEMM_SMEM);
    cudaFuncSetAttribute(attn_mma_kernel,
                         cudaFuncAttributeMaxDynamicSharedMemorySize, ATTN_SMEM);

    split_all_kernel<<<dim3(4096, 6), 256>>>(
        X, xhi, xlo, Wq, wqh, wql, Wk, wkh, wkl, Wv, wvh, wvl, Wo, woh, wol);

    qkv_gemm_kernel<<<dim3(HID / 128, SEQ / 128, 3), 256, GEMM_SMEM>>>(
        xhi, xlo,
        wqh, wql, qhi, qlo,
        wkh, wkl, khi, klo,
        wvh, wvl, vhi, vlo);

    attn_mma_kernel<<<dim3(SEQ / 128, NH), 256, ATTN_SMEM>>>(
        qhi, qlo, khi, klo, vhi, vlo, aohi, aolo);

    reduce_global_kernel<<<dim3(NH, 16), 128>>>(aohi, aolo);

    out_gemm_kernel<<<dim3(HID / 128, SEQ / 128), 256, GEMM_SMEM>>>(
        aohi, aolo, woh, wol, out);
}

// round 17
// speedup vs baseline: 1.6577x; 1.0238x over previous
#include <cuda_runtime.h>
#include <cuda_bf16.h>
#include <math.h>
#include <stdint.h>

#define SEQ      4096
#define HID      2048
#define NH       16
#define HD       128
#define HALF_WIN 256
#define NGLOB    16
#define SCALE    0.08838834764831845f   // 128^-0.5

// GEMM tiling (mma.sync path)
#define KCH        32
#define NKCHUNK    (HID / KCH)       // 64
#define STAGE_B    32768             // Ah 8K | Al 8K | Bh 8K | Bl 8K
#define NSTAGES    3
#define GEMM_SMEM  (NSTAGES * STAGE_B)   // 98304

// Attention smem: Qhi 32K | Qlo 32K | 2 KV stages (64K each) | Qg 8K
#define ATTN_SMEM  (65536 + 2 * 65536 + 8192)   // 204800

// Single dynamic-smem declaration shared by all kernels in this TU.
extern __shared__ __align__(1024) char dyn_smem[];

// ---------------------------------------------------------------------------
// Scratch (device globals: allocation-free rule)
// ---------------------------------------------------------------------------
__device__ __nv_bfloat16 g_Xhi[SEQ * HID], g_Xlo[SEQ * HID];
__device__ __nv_bfloat16 g_Qhi[SEQ * HID], g_Qlo[SEQ * HID];
__device__ __nv_bfloat16 g_Khi[SEQ * HID], g_Klo[SEQ * HID];
__device__ __nv_bfloat16 g_Vhi[SEQ * HID], g_Vlo[SEQ * HID];
__device__ __nv_bfloat16 g_AOhi[SEQ * HID], g_AOlo[SEQ * HID];
__device__ __nv_bfloat16 g_Wqhi[HID * HID], g_Wqlo[HID * HID];
__device__ __nv_bfloat16 g_Wkhi[HID * HID], g_Wklo[HID * HID];
__device__ __nv_bfloat16 g_Wvhi[HID * HID], g_Wvlo[HID * HID];
__device__ __nv_bfloat16 g_Wohi[HID * HID], g_Wolo[HID * HID];

// Global-row partials: [head][xblock(32)][warp(8)] x [16 rows][128 dims]
__device__ float g_partO[NH * 32 * 8 * 16 * HD];
__device__ float g_partML[NH * 32 * 8 * 16 * 2];

// ---------------------------------------------------------------------------
// Helpers (sm_80-compatible PTX only: cp.async, ldmatrix, mma.sync)
// ---------------------------------------------------------------------------
__device__ __forceinline__ uint32_t smem_u32(const void* p) {
    uint32_t a;
    asm("{ .reg .u64 t; cvta.to.shared.u64 t, %1; cvt.u32.u64 %0, t; }" : "=r"(a) : "l"(p));
    return a;
}

__device__ __forceinline__ void cp16(uint32_t dst, const void* src) {
    asm volatile("cp.async.cg.shared.global [%0], [%1], 16;" :: "r"(dst), "l"(src));
}
#define CP_COMMIT() asm volatile("cp.async.commit_group;" ::: "memory")
#define CP_WAIT2()  asm volatile("cp.async.wait_group 2;" ::: "memory")
#define CP_WAIT1()  asm volatile("cp.async.wait_group 1;" ::: "memory")

#define LDSM_X4(r0, r1, r2, r3, addr) \
    asm volatile("ldmatrix.sync.aligned.m8n8.x4.shared.b16 {%0,%1,%2,%3}, [%4];" \
                 : "=r"(r0), "=r"(r1), "=r"(r2), "=r"(r3) : "r"(addr))

#define LDSM_X4_T(r0, r1, r2, r3, addr) \
    asm volatile("ldmatrix.sync.aligned.m8n8.x4.trans.shared.b16 {%0,%1,%2,%3}, [%4];" \
                 : "=r"(r0), "=r"(r1), "=r"(r2), "=r"(r3) : "r"(addr))

#define MMA_BF16(d, a, b) \
    asm volatile("mma.sync.aligned.m16n8k16.row.col.f32.bf16.bf16.f32 " \
                 "{%0,%1,%2,%3}, {%4,%5,%6,%7}, {%8,%9}, {%0,%1,%2,%3};" \
                 : "+f"((d)[0]), "+f"((d)[1]), "+f"((d)[2]), "+f"((d)[3]) \
                 : "r"((a)[0]), "r"((a)[1]), "r"((a)[2]), "r"((a)[3]), \
                   "r"((b)[0]), "r"((b)[1]))

__device__ __forceinline__ uint32_t pack_bf2(__nv_bfloat16 a, __nv_bfloat16 b) {
    return (uint32_t)__bfloat16_as_ushort(a) | ((uint32_t)__bfloat16_as_ushort(b) << 16);
}
__device__ __forceinline__ uint32_t pack_hi(float x, float y) {
    return pack_bf2(__float2bfloat16_rn(x), __float2bfloat16_rn(y));
}
__device__ __forceinline__ uint32_t pack_lo(float x, float y) {
    __nv_bfloat16 hx = __float2bfloat16_rn(x), hy = __float2bfloat16_rn(y);
    return pack_bf2(__float2bfloat16_rn(x - __bfloat162float(hx)),
                    __float2bfloat16_rn(y - __bfloat162float(hy)));
}

// ---------------------------------------------------------------------------
// Merged hi/lo split: grid (2048, 6); y=0,1 cover X halves, y=2..5 weights.
// 8 elements per thread.
// ---------------------------------------------------------------------------
__global__ __launch_bounds__(256) void split_all_kernel(
    const float* __restrict__ X,  __nv_bfloat16* __restrict__ xh,  __nv_bfloat16* __restrict__ xl,
    const float* __restrict__ W0, __nv_bfloat16* __restrict__ w0h, __nv_bfloat16* __restrict__ w0l,
    const float* __restrict__ W1, __nv_bfloat16* __restrict__ w1h, __nv_bfloat16* __restrict__ w1l,
    const float* __restrict__ W2, __nv_bfloat16* __restrict__ w2h, __nv_bfloat16* __restrict__ w2l,
    const float* __restrict__ W3, __nv_bfloat16* __restrict__ w3h, __nv_bfloat16* __restrict__ w3l)
{
    const int y = blockIdx.y;
    const float* src;
    __nv_bfloat16 *hi, *lo;
    size_t base = 0;
    switch (y) {
        case 0: src = X;  hi = xh;  lo = xl;  break;
        case 1: src = X;  hi = xh;  lo = xl;  base = (size_t)SEQ * HID / 2; break;
        case 2: src = W0; hi = w0h; lo = w0l; break;
        case 3: src = W1; hi = w1h; lo = w1l; break;
        case 4: src = W2; hi = w2h; lo = w2l; break;
        default: src = W3; hi = w3h; lo = w3l; break;
    }
    size_t i = base + ((size_t)blockIdx.x * 256 + threadIdx.x) * 8;
    float4 x0 = *(const float4*)(src + i);
    float4 x1 = *(const float4*)(src + i + 4);
    float xs[8] = {x0.x, x0.y, x0.z, x0.w, x1.x, x1.y, x1.z, x1.w};
    __nv_bfloat16 h[8], l[8];
#pragma unroll
    for (int j = 0; j < 8; j++) {
        h[j] = __float2bfloat16_rn(xs[j]);
        l[j] = __float2bfloat16_rn(xs[j] - __bfloat162float(h[j]));
    }
    *(uint4*)(hi + i) = make_uint4(pack_bf2(h[0], h[1]), pack_bf2(h[2], h[3]),
                                   pack_bf2(h[4], h[5]), pack_bf2(h[6], h[7]));
    *(uint4*)(lo + i) = make_uint4(pack_bf2(l[0], l[1]), pack_bf2(l[2], l[3]),
                                   pack_bf2(l[4], l[5]), pack_bf2(l[6], l[7]));
}

// ---------------------------------------------------------------------------
// GEMM chunk loader
// ---------------------------------------------------------------------------
__device__ __forceinline__ void load_chunk(
    uint32_t sbase,
    const __nv_bfloat16* __restrict__ Ahi, const __nv_bfloat16* __restrict__ Alo,
    const __nv_bfloat16* __restrict__ Bhi, const __nv_bfloat16* __restrict__ Blo,
    int mtile, int ntile, int kc, int tid)
{
#pragma unroll
    for (int i = 0; i < 2; i++) {
        int unit = tid + i * 256;
        int r = unit >> 2, u = unit & 3;
        uint32_t dst = sbase + r * 64 + ((u ^ ((r >> 1) & 3)) << 4);
        size_t g = (size_t)(mtile * 128 + r) * HID + kc * KCH + u * 8;
        cp16(dst,        Ahi + g);
        cp16(dst + 8192, Alo + g);
    }
#pragma unroll
    for (int i = 0; i < 2; i++) {
        int unit = tid + i * 256;
        int r = unit >> 4, u = unit & 15;
        uint32_t dst = sbase + 16384 + r * 256 + ((u ^ (r & 7)) << 4);
        size_t g = (size_t)(kc * KCH + r) * HID + ntile * 128 + u * 8;
        cp16(dst,        Bhi + g);
        cp16(dst + 8192, Blo + g);
    }
}

// ---------------------------------------------------------------------------
// bf16 mma.sync GEMM body, 3-term hi/lo compensation.
// R12 pipeline (measured best): wait2 -> sync -> compute -> sync -> load c+3.
// ---------------------------------------------------------------------------
template<bool SPLIT>
__device__ __forceinline__ void gemm_body(
    const __nv_bfloat16* __restrict__ Ahi, const __nv_bfloat16* __restrict__ Alo,
    const __nv_bfloat16* __restrict__ Bhi, const __nv_bfloat16* __restrict__ Blo,
    float* __restrict__ C,
    __nv_bfloat16* __restrict__ Ohi, __nv_bfloat16* __restrict__ Olo,
    int ntile, int mtile)
{
    const uint32_t sb = smem_u32(dyn_smem);
    const int tid  = threadIdx.x;
    const int lane = tid & 31;
    const int wid  = tid >> 5;
    const int wm = (wid & 1) * 64;
    const int wn = (wid >> 1) * 32;

    float acc[4][4][4];
#pragma unroll
    for (int a = 0; a < 4; a++)
#pragma unroll
        for (int b = 0; b < 4; b++)
#pragma unroll
            for (int c = 0; c < 4; c++) acc[a][b][c] = 0.0f;

#pragma unroll
    for (int s = 0; s < NSTAGES; s++) {
        load_chunk(sb + s * STAGE_B, Ahi, Alo, Bhi, Blo, mtile, ntile, s, tid);
        CP_COMMIT();
    }

    for (int c = 0; c < NKCHUNK; c++) {
        const int s = c % NSTAGES;
        const uint32_t sA  = sb + s * STAGE_B;
        const uint32_t sBh = sA + 16384;

        CP_WAIT2();
        __syncthreads();

#pragma unroll
        for (int ks = 0; ks < KCH; ks += 16) {
            uint32_t ah[4][4], bh[4][2], bl[4][2];

            const int brow = ks + (lane & 7) + ((lane >> 3) & 1) * 8;
            const int bnh  = (lane >> 4) * 8;
#pragma unroll
            for (int p = 0; p < 2; p++) {
                const int ncol = wn + p * 16 + bnh;
                uint32_t addr = sBh + brow * 256 + (((ncol >> 3) ^ (brow & 7)) << 4);
                uint32_t r0, r1, r2, r3;
                LDSM_X4_T(r0, r1, r2, r3, addr);
                bh[2 * p][0] = r0; bh[2 * p][1] = r1;
                bh[2 * p + 1][0] = r2; bh[2 * p + 1][1] = r3;
                LDSM_X4_T(r0, r1, r2, r3, addr + 8192);
                bl[2 * p][0] = r0; bl[2 * p][1] = r1;
                bl[2 * p + 1][0] = r2; bl[2 * p + 1][1] = r3;
            }

            const int au = (ks >> 3) + (lane >> 4);
#pragma unroll
            for (int mi = 0; mi < 4; mi++) {
                const int m = wm + mi * 16 + (lane & 15);
                uint32_t addr = sA + m * 64 + ((au ^ ((m >> 1) & 3)) << 4);
                LDSM_X4(ah[mi][0], ah[mi][1], ah[mi][2], ah[mi][3], addr);
            }
#pragma unroll
            for (int mi = 0; mi < 4; mi++)
#pragma unroll
                for (int ni = 0; ni < 4; ni++) {
                    MMA_BF16(acc[mi][ni], ah[mi], bh[ni]);
                    MMA_BF16(acc[mi][ni], ah[mi], bl[ni]);
                }
#pragma unroll
            for (int mi = 0; mi < 4; mi++) {
                const int m = wm + mi * 16 + (lane & 15);
                uint32_t addr = sA + 8192 + m * 64 + ((au ^ ((m >> 1) & 3)) << 4);
                LDSM_X4(ah[mi][0], ah[mi][1], ah[mi][2], ah[mi][3], addr);
            }
#pragma unroll
            for (int mi = 0; mi < 4; mi++)
#pragma unroll
                for (int ni = 0; ni < 4; ni++)
                    MMA_BF16(acc[mi][ni], ah[mi], bh[ni]);
        }

        __syncthreads();
        const int cn = c + NSTAGES;
        if (cn < NKCHUNK)
            load_chunk(sb + s * STAGE_B, Ahi, Alo, Bhi, Blo, mtile, ntile, cn, tid);
        CP_COMMIT();
    }

    const size_t cbase = (size_t)(mtile * 128) * HID + ntile * 128;
#pragma unroll
    for (int mi = 0; mi < 4; mi++) {
#pragma unroll
        for (int ni = 0; ni < 4; ni++) {
            const int r0  = wm + mi * 16 + (lane >> 2);
            const int col = wn + ni * 8 + (lane & 3) * 2;
            const size_t i0 = cbase + (size_t)r0 * HID + col;
            const size_t i1 = i0 + 8 * HID;
            if (SPLIT) {
                *(uint32_t*)&Ohi[i0] = pack_hi(acc[mi][ni][0], acc[mi][ni][1]);
                *(uint32_t*)&Olo[i0] = pack_lo(acc[mi][ni][0], acc[mi][ni][1]);
                *(uint32_t*)&Ohi[i1] = pack_hi(acc[mi][ni][2], acc[mi][ni][3]);
                *(uint32_t*)&Olo[i1] = pack_lo(acc[mi][ni][2], acc[mi][ni][3]);
            } else {
                *(float2*)&C[i0] = make_float2(acc[mi][ni][0], acc[mi][ni][1]);
                *(float2*)&C[i1] = make_float2(acc[mi][ni][2], acc[mi][ni][3]);
            }
        }
    }
}

// QKV: one launch, grid (16, 32, 3); z selects weight + destination.
__global__ __launch_bounds__(256, 2) void qkv_gemm_kernel(
    const __nv_bfloat16* __restrict__ Ahi, const __nv_bfloat16* __restrict__ Alo,
    const __nv_bfloat16* __restrict__ W0h, const __nv_bfloat16* __restrict__ W0l,
    __nv_bfloat16* __restrict__ O0h, __nv_bfloat16* __restrict__ O0l,
    const __nv_bfloat16* __restrict__ W1h, const __nv_bfloat16* __restrict__ W1l,
    __nv_bfloat16* __restrict__ O1h, __nv_bfloat16* __restrict__ O1l,
    const __nv_bfloat16* __restrict__ W2h, const __nv_bfloat16* __restrict__ W2l,
    __nv_bfloat16* __restrict__ O2h, __nv_bfloat16* __restrict__ O2l)
{
    const __nv_bfloat16 *bh, *bl;
    __nv_bfloat16 *oh, *ol;
    if (blockIdx.z == 0)      { bh = W0h; bl = W0l; oh = O0h; ol = O0l; }
    else if (blockIdx.z == 1) { bh = W1h; bl = W1l; oh = O1h; ol = O1l; }
    else                      { bh = W2h; bl = W2l; oh = O2h; ol = O2l; }
    gemm_body<true>(Ahi, Alo, bh, bl, nullptr, oh, ol, blockIdx.x, blockIdx.y);
}

__global__ __launch_bounds__(256, 2) void out_gemm_kernel(
    const __nv_bfloat16* __restrict__ Ahi, const __nv_bfloat16* __restrict__ Alo,
    const __nv_bfloat16* __restrict__ Bhi, const __nv_bfloat16* __restrict__ Blo,
    float* __restrict__ C)
{
    gemm_body<false>(Ahi, Alo, Bhi, Blo, C, nullptr, nullptr, blockIdx.x, blockIdx.y);
}

// ---------------------------------------------------------------------------
// Flash attention, mma.sync bf16 with hi/lo compensation (R16 structure).
// ---------------------------------------------------------------------------
__device__ __forceinline__ void attn_load_kv(
    uint32_t kvb, int t, int tid, int h,
    const __nv_bfloat16* __restrict__ Khi, const __nv_bfloat16* __restrict__ Klo,
    const __nv_bfloat16* __restrict__ Vhi, const __nv_bfloat16* __restrict__ Vlo)
{
#pragma unroll
    for (int i = 0; i < 4; i++) {
        int u = tid + 256 * i;
        int r = u >> 4, c = u & 15;
        size_t g = (size_t)(t * 64 + r) * HID + h * HD + c * 8;
        uint32_t dst = kvb + r * 256 + ((c ^ (r & 7)) << 4);
        cp16(dst,         Khi + g);
        cp16(dst + 16384, Klo + g);
        cp16(dst + 32768, Vhi + g);
        cp16(dst + 49152, Vlo + g);
    }
}

__global__ __launch_bounds__(256, 1) void attn_mma_kernel(
    const __nv_bfloat16* __restrict__ Qhi, const __nv_bfloat16* __restrict__ Qlo,
    const __nv_bfloat16* __restrict__ Khi, const __nv_bfloat16* __restrict__ Klo,
    const __nv_bfloat16* __restrict__ Vhi, const __nv_bfloat16* __restrict__ Vlo,
    __nv_bfloat16* __restrict__ Ohi, __nv_bfloat16* __restrict__ Olo)
{
    const uint32_t sb  = smem_u32(dyn_smem);
    const uint32_t SQ  = sb;                     // Qhi 32K, Qlo at +32768
    const uint32_t SQG = sb + 196608;            // global-row Q: hi 4K, lo 4K
    const int tid = threadIdx.x, lane = tid & 31, wid = tid >> 5;
    const int wm = wid * 16;
    const int q0 = blockIdx.x * 128;
    const int h  = blockIdx.y;
    const int lr = lane & 15, lc = (lane >> 4) * 8;

    // Q tile load (hi+lo) + global-row Q (rows 0..15)
#pragma unroll
    for (int i = 0; i < 8; i++) {
        int u = tid + 256 * i;
        int r = u >> 4, c = u & 15;
        size_t g = (size_t)(q0 + r) * HID + h * HD + c * 8;
        uint32_t dst = SQ + r * 256 + ((c ^ (r & 7)) << 4);
        cp16(dst,         Qhi + g);
        cp16(dst + 32768, Qlo + g);
    }
    {
        int r = tid >> 4, c = tid & 15;   // rows 0..15
        size_t g = (size_t)r * HID + h * HD + c * 8;
        uint32_t dst = SQG + r * 256 + ((c ^ (r & 7)) << 4);
        cp16(dst,        Qhi + g);
        cp16(dst + 4096, Qlo + g);
    }
    CP_COMMIT();

    int t_lo, t_hi;
    {
        int lo = q0 - (HALF_WIN - 1);
        t_lo = (lo < 64) ? 1 : (lo >> 6);
        t_hi = (q0 + 127 + HALF_WIN - 1) >> 6;
        if (t_hi > 63) t_hi = 63;
    }
    const int n_tiles = t_hi - t_lo + 2;   // tile(0)=0 (global keys), then band

    attn_load_kv(sb + 65536, 0, tid, h, Khi, Klo, Vhi, Vlo);
    CP_COMMIT();

    float m0 = -INFINITY, m1 = -INFINITY, l0 = 0.0f, l1 = 0.0f;
    float ov[16][4];
#pragma unroll
    for (int n = 0; n < 16; n++)
#pragma unroll
        for (int c = 0; c < 4; c++) ov[n][c] = 0.0f;

    const int r0g = q0 + wm + (lane >> 2);
    const int r1g = r0g + 8;
    const int t_self = 2 * blockIdx.x + (wid >> 2);   // this warp's global key tile
    const int troff  = (wid & 3) * 16;                // 16-key slice within tile

    for (int it = 0; it < n_tiles; it++) {
        const int s = it & 1;
        const uint32_t kvb = sb + 65536 + s * 65536;

        __syncthreads();               // prev compute done before stage reuse
        if (it + 1 < n_tiles)
            attn_load_kv(sb + 65536 + (s ^ 1) * 65536, t_lo + it, tid, h,
                         Khi, Klo, Vhi, Vlo);
        CP_COMMIT();
        CP_WAIT1();
        __syncthreads();               // current tile (and Q) visible

        const int t   = (it == 0) ? 0 : (t_lo + it - 1);
        const int kv0 = t << 6;

        // ---- S = Q K^T (3-term) ----
        float sv[8][4];
#pragma unroll
        for (int j = 0; j < 8; j++)
#pragma unroll
            for (int c = 0; c < 4; c++) sv[j][c] = 0.0f;

#pragma unroll
        for (int ks = 0; ks < 8; ks++) {
            uint32_t qh[4], ql[4];
            {
                int r = wm + lr, d = 16 * ks + lc;
                uint32_t a = SQ + r * 256 + (((d >> 3) ^ (r & 7)) << 4);
                LDSM_X4(qh[0], qh[1], qh[2], qh[3], a);
                LDSM_X4(ql[0], ql[1], ql[2], ql[3], a + 32768);
            }
#pragma unroll
            for (int j4 = 0; j4 < 4; j4++) {
                uint32_t kh[4], kl[4];
                int r = 16 * j4 + lr, d = 16 * ks + lc;
                uint32_t a = kvb + r * 256 + (((d >> 3) ^ (r & 7)) << 4);
                LDSM_X4(kh[0], kh[1], kh[2], kh[3], a);
                LDSM_X4(kl[0], kl[1], kl[2], kl[3], a + 16384);
                uint32_t b0[2] = {kh[0], kh[2]}, b1[2] = {kh[1], kh[3]};
                uint32_t c0[2] = {kl[0], kl[2]}, c1[2] = {kl[1], kl[3]};
                MMA_BF16(sv[2 * j4],     qh, b0);
                MMA_BF16(sv[2 * j4],     qh, c0);
                MMA_BF16(sv[2 * j4],     ql, b0);
                MMA_BF16(sv[2 * j4 + 1], qh, b1);
                MMA_BF16(sv[2 * j4 + 1], qh, c1);
                MMA_BF16(sv[2 * j4 + 1], ql, b1);
            }
        }

        // ---- scale + mask ----
#pragma unroll
        for (int j = 0; j < 8; j++) {
            const int kc = kv0 + 8 * j + (lane & 3) * 2;
#pragma unroll
            for (int c = 0; c < 4; c++) {
                const int qi = (c < 2) ? r0g : r1g;
                const int kj = kc + (c & 1);
                const int d  = qi - kj;
                const bool ok = (d < HALF_WIN && d > -HALF_WIN) ||
                                (qi < NGLOB) || (kj < NGLOB);
                sv[j][c] = ok ? sv[j][c] * SCALE : -INFINITY;
            }
        }

        // ---- online softmax (2 rows per thread) ----
        float mx0 = -INFINITY, mx1 = -INFINITY;
#pragma unroll
        for (int j = 0; j < 8; j++) {
            mx0 = fmaxf(mx0, fmaxf(sv[j][0], sv[j][1]));
            mx1 = fmaxf(mx1, fmaxf(sv[j][2], sv[j][3]));
        }
        mx0 = fmaxf(mx0, __shfl_xor_sync(0xffffffffu, mx0, 1));
        mx0 = fmaxf(mx0, __shfl_xor_sync(0xffffffffu, mx0, 2));
        mx1 = fmaxf(mx1, __shfl_xor_sync(0xffffffffu, mx1, 1));
        mx1 = fmaxf(mx1, __shfl_xor_sync(0xffffffffu, mx1, 2));

        const float mn0 = fmaxf(m0, mx0), mn1 = fmaxf(m1, mx1);
        const float cr0 = __expf(m0 - mn0), cr1 = __expf(m1 - mn1);
        float s0 = 0.0f, s1 = 0.0f;
#pragma unroll
        for (int j = 0; j < 8; j++) {
            sv[j][0] = __expf(sv[j][0] - mn0);
            sv[j][1] = __expf(sv[j][1] - mn0);
            sv[j][2] = __expf(sv[j][2] - mn1);
            sv[j][3] = __expf(sv[j][3] - mn1);
            s0 += sv[j][0] + sv[j][1];
            s1 += sv[j][2] + sv[j][3];
        }
        s0 += __shfl_xor_sync(0xffffffffu, s0, 1);
        s0 += __shfl_xor_sync(0xffffffffu, s0, 2);
        s1 += __shfl_xor_sync(0xffffffffu, s1, 1);
        s1 += __shfl_xor_sync(0xffffffffu, s1, 2);
        l0 = l0 * cr0 + s0;  m0 = mn0;
        l1 = l1 * cr1 + s1;  m1 = mn1;
#pragma unroll
        for (int n = 0; n < 16; n++) {
            ov[n][0] *= cr0; ov[n][1] *= cr0;
            ov[n][2] *= cr1; ov[n][3] *= cr1;
        }

        // ---- P fragments (hi/lo) directly from S registers ----
        uint32_t phi[4][4], plo[4][4];
#pragma unroll
        for (int t2 = 0; t2 < 4; t2++) {
            phi[t2][0] = pack_hi(sv[2 * t2][0],     sv[2 * t2][1]);
            plo[t2][0] = pack_lo(sv[2 * t2][0],     sv[2 * t2][1]);
            phi[t2][1] = pack_hi(sv[2 * t2][2],     sv[2 * t2][3]);
            plo[t2][1] = pack_lo(sv[2 * t2][2],     sv[2 * t2][3]);
            phi[t2][2] = pack_hi(sv[2 * t2 + 1][0], sv[2 * t2 + 1][1]);
            plo[t2][2] = pack_lo(sv[2 * t2 + 1][0], sv[2 * t2 + 1][1]);
            phi[t2][3] = pack_hi(sv[2 * t2 + 1][2], sv[2 * t2 + 1][3]);
            plo[t2][3] = pack_lo(sv[2 * t2 + 1][2], sv[2 * t2 + 1][3]);
        }

        // ---- O += P V (3-term) ----
#pragma unroll
        for (int t2 = 0; t2 < 4; t2++) {
#pragma unroll
            for (int jj = 0; jj < 8; jj++) {
                uint32_t vh[4], vl[4];
                int r = 16 * t2 + lr, d = 16 * jj + lc;
                uint32_t a = kvb + 32768 + r * 256 + (((d >> 3) ^ (r & 7)) << 4);
                LDSM_X4_T(vh[0], vh[1], vh[2], vh[3], a);
                LDSM_X4_T(vl[0], vl[1], vl[2], vl[3], a + 16384);
                uint32_t b0[2] = {vh[0], vh[1]}, b1[2] = {vh[2], vh[3]};
                uint32_t c0[2] = {vl[0], vl[1]}, c1[2] = {vl[2], vl[3]};
                MMA_BF16(ov[2 * jj],     phi[t2], b0);
                MMA_BF16(ov[2 * jj],     plo[t2], b0);
                MMA_BF16(ov[2 * jj],     phi[t2], c0);
                MMA_BF16(ov[2 * jj + 1], phi[t2], b1);
                MMA_BF16(ov[2 * jj + 1], plo[t2], b1);
                MMA_BF16(ov[2 * jj + 1], phi[t2], c1);
            }
        }

        // ---- global-row partial over this warp's 16-key slice ----
        if (t == t_self) {
            float sg[2][4];
#pragma unroll
            for (int j = 0; j < 2; j++)
#pragma unroll
                for (int c = 0; c < 4; c++) sg[j][c] = 0.0f;

#pragma unroll
            for (int ks = 0; ks < 8; ks++) {
                uint32_t qgh[4], qgl[4], kh[4], kl[4];
                int d = 16 * ks + lc;
                uint32_t qa = SQG + lr * 256 + (((d >> 3) ^ (lr & 7)) << 4);
                LDSM_X4(qgh[0], qgh[1], qgh[2], qgh[3], qa);
                LDSM_X4(qgl[0], qgl[1], qgl[2], qgl[3], qa + 4096);
                int r = troff + lr;
                uint32_t ka = kvb + r * 256 + (((d >> 3) ^ (r & 7)) << 4);
                LDSM_X4(kh[0], kh[1], kh[2], kh[3], ka);
                LDSM_X4(kl[0], kl[1], kl[2], kl[3], ka + 16384);
                uint32_t b0[2] = {kh[0], kh[2]}, b1[2] = {kh[1], kh[3]};
                uint32_t c0[2] = {kl[0], kl[2]}, c1[2] = {kl[1], kl[3]};
                MMA_BF16(sg[0], qgh, b0);
                MMA_BF16(sg[0], qgh, c0);
                MMA_BF16(sg[0], qgl, b0);
                MMA_BF16(sg[1], qgh, b1);
                MMA_BF16(sg[1], qgh, c1);
                MMA_BF16(sg[1], qgl, b1);
            }
#pragma unroll
            for (int j = 0; j < 2; j++)
#pragma unroll
                for (int c = 0; c < 4; c++) sg[j][c] *= SCALE;

            float mg0 = fmaxf(fmaxf(sg[0][0], sg[0][1]), fmaxf(sg[1][0], sg[1][1]));
            float mg1 = fmaxf(fmaxf(sg[0][2], sg[0][3]), fmaxf(sg[1][2], sg[1][3]));
            mg0 = fmaxf(mg0, __shfl_xor_sync(0xffffffffu, mg0, 1));
            mg0 = fmaxf(mg0, __shfl_xor_sync(0xffffffffu, mg0, 2));
            mg1 = fmaxf(mg1, __shfl_xor_sync(0xffffffffu, mg1, 1));
            mg1 = fmaxf(mg1, __shfl_xor_sync(0xffffffffu, mg1, 2));
            float lg0 = 0.0f, lg1 = 0.0f;
#pragma unroll
            for (int j = 0; j < 2; j++) {
                sg[j][0] = __expf(sg[j][0] - mg0);
                sg[j][1] = __expf(sg[j][1] - mg0);
                sg[j][2] = __expf(sg[j][2] - mg1);
                sg[j][3] = __expf(sg[j][3] - mg1);
                lg0 += sg[j][0] + sg[j][1];
                lg1 += sg[j][2] + sg[j][3];
            }
            lg0 += __shfl_xor_sync(0xffffffffu, lg0, 1);
            lg0 += __shfl_xor_sync(0xffffffffu, lg0, 2);
            lg1 += __shfl_xor_sync(0xffffffffu, lg1, 1);
            lg1 += __shfl_xor_sync(0xffffffffu, lg1, 2);

            uint32_t pgh[4], pgl[4];
            pgh[0] = pack_hi(sg[0][0], sg[0][1]); pgl[0] = pack_lo(sg[0][0], sg[0][1]);
            pgh[1] = pack_hi(sg[0][2], sg[0][3]); pgl[1] = pack_lo(sg[0][2], sg[0][3]);
            pgh[2] = pack_hi(sg[1][0], sg[1][1]); pgl[2] = pack_lo(sg[1][0], sg[1][1]);
            pgh[3] = pack_hi(sg[1][2], sg[1][3]); pgl[3] = pack_lo(sg[1][2], sg[1][3]);

            float og[16][4];
#pragma unroll
            for (int n = 0; n < 16; n++)
#pragma unroll
                for (int c = 0; c < 4; c++) og[n][c] = 0.0f;

#pragma unroll
            for (int nf = 0; nf < 8; nf++) {
                uint32_t vh[4], vl[4];
                int r = troff + lr, d = 16 * nf + lc;
                uint32_t a = kvb + 32768 + r * 256 + (((d >> 3) ^ (r & 7)) << 4);
                LDSM_X4_T(vh[0], vh[1], vh[2], vh[3], a);
                LDSM_X4_T(vl[0], vl[1], vl[2], vl[3], a + 16384);
                uint32_t b0[2] = {vh[0], vh[1]}, b1[2] = {vh[2], vh[3]};
                uint32_t c0[2] = {vl[0], vl[1]}, c1[2] = {vl[2], vl[3]};
                MMA_BF16(og[2 * nf],     pgh, b0);
                MMA_BF16(og[2 * nf],     pgl, b0);
                MMA_BF16(og[2 * nf],     pgh, c0);
                MMA_BF16(og[2 * nf + 1], pgh, b1);
                MMA_BF16(og[2 * nf + 1], pgl, b1);
                MMA_BF16(og[2 * nf + 1], pgh, c1);
            }

            const int r0l = lane >> 2, c0l = (lane & 3) * 2;
            float* PB = g_partO +
                (size_t)(((h * 32 + blockIdx.x) * 8) + wid) * (16 * HD);
#pragma unroll
            for (int n = 0; n < 16; n++) {
                *(float2*)&PB[r0l * HD + n * 8 + c0l] =
                    make_float2(og[n][0], og[n][1]);
                *(float2*)&PB[(r0l + 8) * HD + n * 8 + c0l] =
                    make_float2(og[n][2], og[n][3]);
            }
            if ((lane & 3) == 0) {
                float* MB = g_partML +
                    (size_t)((((h * 32 + blockIdx.x) * 8) + wid) * 16) * 2;
                MB[r0l * 2]           = mg0;
                MB[r0l * 2 + 1]       = lg0;
                MB[(r0l + 8) * 2]     = mg1;
                MB[(r0l + 8) * 2 + 1] = lg1;
            }
        }
    }

    // ---- epilogue: normalize and write hi/lo bf16 ----
    if (!(q0 == 0 && wid == 0)) {
        const float inv0 = 1.0f / l0, inv1 = 1.0f / l1;
        const size_t base0 = (size_t)r0g * HID + h * HD + (lane & 3) * 2;
        const size_t base1 = base0 + (size_t)8 * HID;
#pragma unroll
        for (int n = 0; n < 16; n++) {
            float x0 = ov[n][0] * inv0, x1 = ov[n][1] * inv0;
            float y0 = ov[n][2] * inv1, y1 = ov[n][3] * inv1;
            *(uint32_t*)&Ohi[base0 + 8 * n] = pack_hi(x0, x1);
            *(uint32_t*)&Olo[base0 + 8 * n] = pack_lo(x0, x1);
            *(uint32_t*)&Ohi[base1 + 8 * n] = pack_hi(y0, y1);
            *(uint32_t*)&Olo[base1 + 8 * n] = pack_lo(y0, y1);
        }
    }
}

// ---------------------------------------------------------------------------
// Merge 256 global-row partials per head; write rows 0..15 of AO.
// grid (NH, 16 rows), 256 threads: two 128-partial halves x 128 dims,
// 4 independent accumulators for MLP.
// ---------------------------------------------------------------------------
__global__ __launch_bounds__(256) void reduce_global_kernel(
    __nv_bfloat16* __restrict__ Ohi, __nv_bfloat16* __restrict__ Olo)
{
    __shared__ float sm[256], sl[256], swe[256], spart[128], swm[8];
    const int h = blockIdx.x, r = blockIdx.y, tid = threadIdx.x;

    {
        const float* MB = g_partML + ((size_t)(h * 256 + tid) * 16 + r) * 2;
        sm[tid] = MB[0];
        sl[tid] = MB[1];
    }
    __syncthreads();

    float M = sm[tid];
#pragma unroll
    for (int o = 16; o; o >>= 1)
        M = fmaxf(M, __shfl_xor_sync(0xffffffffu, M, o));
    if ((tid & 31) == 0) swm[tid >> 5] = M;
    __syncthreads();
    M = swm[0];
#pragma unroll
    for (int w = 1; w < 8; w++) M = fmaxf(M, swm[w]);

    swe[tid] = __expf(sm[tid] - M);
    __syncthreads();

    float L0 = 0.0f, L1 = 0.0f, L2 = 0.0f, L3 = 0.0f;
#pragma unroll
    for (int p = 0; p < 256; p += 4) {
        L0 += swe[p + 0] * sl[p + 0];
        L1 += swe[p + 1] * sl[p + 1];
        L2 += swe[p + 2] * sl[p + 2];
        L3 += swe[p + 3] * sl[p + 3];
    }
    const float L = (L0 + L1) + (L2 + L3);

    const int half = tid >> 7;
    const int d    = tid & 127;
    const float* base = g_partO +
        ((size_t)(h * 256 + half * 128) * 16 + r) * HD + d;
    const float* we = swe + half * 128;
    float a0 = 0.0f, a1 = 0.0f, a2 = 0.0f, a3 = 0.0f;
#pragma unroll 8
    for (int p = 0; p < 128; p += 4) {
        a0 += we[p + 0] * base[(size_t)(p + 0) * 16 * HD];
        a1 += we[p + 1] * base[(size_t)(p + 1) * 16 * HD];
        a2 += we[p + 2] * base[(size_t)(p + 2) * 16 * HD];
        a3 += we[p + 3] * base[(size_t)(p + 3) * 16 * HD];
    }
    float s = (a0 + a1) + (a2 + a3);

    if (half) spart[d] = s;
    __syncthreads();
    if (!half) {
        s += spart[d];
        const float o = s / L;
        const size_t idx = (size_t)r * HID + h * HD + d;
        __nv_bfloat16 hi = __float2bfloat16_rn(o);
        Ohi[idx] = hi;
        Olo[idx] = __float2bfloat16_rn(o - __bfloat162float(hi));
    }
}

// ---------------------------------------------------------------------------

extern "C" void kernel_launch(void* const* d_in, const int* in_sizes, int n_in,
                              void* d_out, int out_size)
{
    const float* X  = (const float*)d_in[0];
    const float* Wq = (const float*)d_in[1];
    const float* Wk = (const float*)d_in[2];
    const float* Wv = (const float*)d_in[3];
    const float* Wo = (const float*)d_in[4];
    float* out = (float*)d_out;

    __nv_bfloat16 *xhi, *xlo, *qhi, *qlo, *khi, *klo, *vhi, *vlo, *aohi, *aolo;
    __nv_bfloat16 *wqh, *wql, *wkh, *wkl, *wvh, *wvl, *woh, *wol;
    cudaGetSymbolAddress((void**)&xhi,  g_Xhi);
    cudaGetSymbolAddress((void**)&xlo,  g_Xlo);
    cudaGetSymbolAddress((void**)&qhi,  g_Qhi);
    cudaGetSymbolAddress((void**)&qlo,  g_Qlo);
    cudaGetSymbolAddress((void**)&khi,  g_Khi);
    cudaGetSymbolAddress((void**)&klo,  g_Klo);
    cudaGetSymbolAddress((void**)&vhi,  g_Vhi);
    cudaGetSymbolAddress((void**)&vlo,  g_Vlo);
    cudaGetSymbolAddress((void**)&aohi, g_AOhi);
    cudaGetSymbolAddress((void**)&aolo, g_AOlo);
    cudaGetSymbolAddress((void**)&wqh,  g_Wqhi);
    cudaGetSymbolAddress((void**)&wql,  g_Wqlo);
    cudaGetSymbolAddress((void**)&wkh,  g_Wkhi);
    cudaGetSymbolAddress((void**)&wkl,  g_Wklo);
    cudaGetSymbolAddress((void**)&wvh,  g_Wvhi);
    cudaGetSymbolAddress((void**)&wvl,  g_Wvlo);
    cudaGetSymbolAddress((void**)&woh,  g_Wohi);
    cudaGetSymbolAddress((void**)&wol,  g_Wolo);

    cudaFuncSetAttribute(qkv_gemm_kernel,
                         cudaFuncAttributeMaxDynamicSharedMemorySize, GEMM_SMEM);
    cudaFuncSetAttribute(out_gemm_kernel,
                         cudaFuncAttributeMaxDynamicSharedMemorySize, GEMM_SMEM);
    cudaFuncSetAttribute(attn_mma_kernel,
                         cudaFuncAttributeMaxDynamicSharedMemorySize, ATTN_SMEM);

    split_all_kernel<<<dim3(2048, 6), 256>>>(
        X, xhi, xlo, Wq, wqh, wql, Wk, wkh, wkl, Wv, wvh, wvl, Wo, woh, wol);

    qkv_gemm_kernel<<<dim3(HID / 128, SEQ / 128, 3), 256, GEMM_SMEM>>>(
        xhi, xlo,
        wqh, wql, qhi, qlo,
        wkh, wkl, khi, klo,
        wvh, wvl, vhi, vlo);

    attn_mma_kernel<<<dim3(SEQ / 128, NH), 256, ATTN_SMEM>>>(
        qhi, qlo, khi, klo, vhi, vlo, aohi, aolo);

    reduce_global_kernel<<<dim3(NH, 16), 256>>>(aohi, aolo);

    out_gemm_kernel<<<dim3(HID / 128, SEQ / 128), 256, GEMM_SMEM>>>(
        aohi, aolo, woh, wol, out);
}